// round 8
// baseline (speedup 1.0000x reference)
#include <cuda_runtime.h>
#include <cuda_bf16.h>
#include <math.h>
#include <stdint.h>

// ---------------- problem constants ----------------------------------------
#define BSZ 2
#define TT 2048
#define DM 1024
#define DI 2048
#define NH 8
#define DS 64
#define DH 256
#define NROWS (BSZ*TT)          // 4096
#define EPSV 1e-6f
#define NCATP 1152              // B(512) | C(512) | dt(8) | pad -> 9*128

// ---------------- scratch (device globals) ---------------------------------
__device__ __nv_bfloat16 g_xn[(size_t)NROWS * DM];
__device__ float         g_xz[(size_t)NROWS * 2 * DI];
__device__ __nv_bfloat16 g_xs[(size_t)NROWS * DI];
__device__ float         g_bcdt[(size_t)NROWS * NCATP];
__device__ float         g_dt[(size_t)NROWS * NH];
__device__ __nv_bfloat16 g_y [(size_t)NROWS * DI];
__device__ __nv_bfloat16 g_inw [(size_t)(2*DI) * DM];
__device__ __nv_bfloat16 g_wcat[(size_t)NCATP * DI];
__device__ __nv_bfloat16 g_outw[(size_t)DM * DI];

// ---------------- PTX helpers ----------------------------------------------
__device__ __forceinline__ uint32_t smem_u32(const void* p) {
    uint32_t a;
    asm("{ .reg .u64 t; cvta.to.shared.u64 t, %1; cvt.u32.u64 %0, t; }" : "=r"(a) : "l"(p));
    return a;
}

#define CP_ASYNC16(dst, src) \
    asm volatile("cp.async.cg.shared.global [%0], [%1], 16;" :: "r"(dst), "l"(src) : "memory")
#define CP_ASYNC4(dst, src) \
    asm volatile("cp.async.ca.shared.global [%0], [%1], 4;" :: "r"(dst), "l"(src) : "memory")
#define CP_COMMIT() asm volatile("cp.async.commit_group;" ::: "memory")
#define CP_WAIT1()  asm volatile("cp.async.wait_group 1;" ::: "memory")

#define LDM_X4(r0, r1, r2, r3, addr) \
    asm volatile("ldmatrix.sync.aligned.m8n8.x4.shared.b16 {%0,%1,%2,%3}, [%4];" \
                 : "=r"(r0), "=r"(r1), "=r"(r2), "=r"(r3) : "r"(addr))

#define MMA16816(d, a0, a1, a2, a3, b0, b1) \
    asm volatile("mma.sync.aligned.m16n8k16.row.col.f32.bf16.bf16.f32 " \
                 "{%0,%1,%2,%3}, {%4,%5,%6,%7}, {%8,%9}, {%0,%1,%2,%3};" \
                 : "+f"((d)[0]), "+f"((d)[1]), "+f"((d)[2]), "+f"((d)[3]) \
                 : "r"(a0), "r"(a1), "r"(a2), "r"(a3), "r"(b0), "r"(b1))

// ---------------- bf16 mma.sync GEMM: C[M,N] = A[M,K] @ W[N,K]^T (+Res) ----
// BM=BN=128, BK=64, 3-stage cp.async ring, 128 threads, 4 warps (2x2),
// warp tile 64x64. One __syncthreads per K-tile; loads overlap compute.
#define BM 128
#define BN 128
#define BK64 64
#define ROWB 144                         // 64*2 + 16 pad bytes
#define SA_BYTES (BM * ROWB)             // 18432
#define STG_BYTES (2 * SA_BYTES)         // 36864 (A + B)
#define NST 3
#define GEMM_SMEM (NST * STG_BYTES)      // 110592

template <bool ADD_RES>
__global__ void __launch_bounds__(128)
gemm_mma(const __nv_bfloat16* __restrict__ A, const __nv_bfloat16* __restrict__ W,
         float* __restrict__ C, const float* __restrict__ Res,
         int M, int N, int K)
{
    extern __shared__ char sm[];
    uint32_t base = smem_u32(sm);

    int tid = threadIdx.x;
    int wid = tid >> 5, lane = tid & 31;
    int wm = wid >> 1, wn = wid & 1;          // 2 x 2 warp grid, tile 64x64
    int m0 = blockIdx.y * BM;
    int n0 = blockIdx.x * BN;

    const __nv_bfloat16* Ag = A + (size_t)m0 * K;
    const __nv_bfloat16* Wg = W + (size_t)n0 * K;

    float acc[4][8][4];
    #pragma unroll
    for (int i = 0; i < 4; i++)
        #pragma unroll
        for (int j = 0; j < 8; j++)
            #pragma unroll
            for (int f = 0; f < 4; f++) acc[i][j][f] = 0.f;

    int nk = K / BK64;

    // stage loader: A and B each 128 rows x 8 16B-chunks = 1024 chunks
    auto load_stage = [&](int s, int k0) {
        uint32_t sA = base + s * STG_BYTES;
        uint32_t sB = sA + SA_BYTES;
        #pragma unroll
        for (int it = 0; it < 8; it++) {
            int i = tid + it * 128;
            int r = i >> 3, c = i & 7;
            CP_ASYNC16(sA + r * ROWB + c * 16, Ag + (size_t)r * K + k0 + c * 8);
        }
        #pragma unroll
        for (int it = 0; it < 8; it++) {
            int i = tid + it * 128;
            int r = i >> 3, c = i & 7;
            CP_ASYNC16(sB + r * ROWB + c * 16, Wg + (size_t)r * K + k0 + c * 8);
        }
    };

    load_stage(0, 0);      CP_COMMIT();
    load_stage(1, BK64);   CP_COMMIT();

    int stg = 0;                      // stage index of tile kt (mod 3)
    for (int kt = 0; kt < nk; kt++) {
        CP_WAIT1();                   // stage kt complete
        __syncthreads();

        // issue loads for tile kt+2 (overlaps with compute below)
        int s2 = stg + 2; if (s2 >= NST) s2 -= NST;
        if (kt + 2 < nk) load_stage(s2, (kt + 2) * BK64);
        CP_COMMIT();                  // always commit (group accounting)

        uint32_t sA = base + stg * STG_BYTES;
        uint32_t sB = sA + SA_BYTES;

        #pragma unroll
        for (int ks = 0; ks < 4; ks++) {
            int colb = ks * 32 + (lane >> 4) * 16;           // bytes
            uint32_t a[4][4], b[4][4];
            #pragma unroll
            for (int i = 0; i < 4; i++) {
                int row = wm * 64 + i * 16 + (lane & 15);
                LDM_X4(a[i][0], a[i][1], a[i][2], a[i][3],
                       sA + (uint32_t)(row * ROWB + colb));
            }
            #pragma unroll
            for (int jj = 0; jj < 4; jj++) {
                int row = wn * 64 + jj * 16 + (lane & 15);
                LDM_X4(b[jj][0], b[jj][1], b[jj][2], b[jj][3],
                       sB + (uint32_t)(row * ROWB + colb));
            }
            #pragma unroll
            for (int i = 0; i < 4; i++)
                #pragma unroll
                for (int jj = 0; jj < 4; jj++) {
                    MMA16816(acc[i][jj * 2],     a[i][0], a[i][1], a[i][2], a[i][3],
                             b[jj][0], b[jj][2]);
                    MMA16816(acc[i][jj * 2 + 1], a[i][0], a[i][1], a[i][2], a[i][3],
                             b[jj][1], b[jj][3]);
                }
        }
        stg++; if (stg >= NST) stg -= NST;
    }

    // epilogue: direct register -> gmem (float2 per c-frag half)
    int gid = lane >> 2, t4 = lane & 3;
    #pragma unroll
    for (int i = 0; i < 4; i++) {
        int row0 = m0 + wm * 64 + i * 16 + gid;
        #pragma unroll
        for (int j = 0; j < 8; j++) {
            int col = n0 + wn * 64 + j * 8 + t4 * 2;
            size_t i0 = (size_t)row0 * N + col;
            size_t i1 = (size_t)(row0 + 8) * N + col;
            float2 v0 = make_float2(acc[i][j][0], acc[i][j][1]);
            float2 v1 = make_float2(acc[i][j][2], acc[i][j][3]);
            if (ADD_RES) {
                float2 r0 = *(const float2*)(Res + i0);
                float2 r1 = *(const float2*)(Res + i1);
                v0.x += r0.x; v0.y += r0.y;
                v1.x += r1.x; v1.y += r1.y;
            }
            *(float2*)(C + i0) = v0;
            *(float2*)(C + i1) = v1;
        }
    }
}

// ---------------- weight conversion ----------------------------------------
__global__ void cvt_bf16_k(const float* __restrict__ in, __nv_bfloat16* __restrict__ out, int n)
{
    for (int i = blockIdx.x * 256 + threadIdx.x; i < n; i += gridDim.x * 256)
        out[i] = __float2bfloat16(in[i]);
}

__global__ void build_wcat_k(const float* __restrict__ Bw, const float* __restrict__ Cw,
                             const float* __restrict__ dtw)
{
    int n = NCATP * DI;
    for (int i = blockIdx.x * 256 + threadIdx.x; i < n; i += gridDim.x * 256) {
        int r = i >> 11, k = i & (DI - 1);
        float v;
        if (r < 512)       v = Bw[(size_t)r * DI + k];
        else if (r < 1024) v = Cw[(size_t)(r - 512) * DI + k];
        else if (r < 1032) v = dtw[(size_t)(r - 1024) * DI + k];
        else               v = 0.f;
        g_wcat[i] = __float2bfloat16(v);
    }
}

// ---------------- RMSNorm (writes bf16) -------------------------------------
__global__ void rmsnorm_k(const float* __restrict__ x, const float* __restrict__ w)
{
    int row = blockIdx.x;
    const float* xr = x + (size_t)row * DM;
    float s = 0.f;
    for (int i = threadIdx.x; i < DM; i += 256) { float v = xr[i]; s += v * v; }
    __shared__ float red[8];
    #pragma unroll
    for (int o = 16; o; o >>= 1) s += __shfl_xor_sync(0xffffffffu, s, o);
    if ((threadIdx.x & 31) == 0) red[threadIdx.x >> 5] = s;
    __syncthreads();
    if (threadIdx.x < 8) {
        float v = red[threadIdx.x];
        #pragma unroll
        for (int o = 4; o; o >>= 1) v += __shfl_xor_sync(0xffu, v, o);
        if (threadIdx.x == 0) red[0] = rsqrtf(v / (float)DM + EPSV);
    }
    __syncthreads();
    float sc = red[0];
    for (int i = threadIdx.x; i < DM; i += 256)
        g_xn[(size_t)row * DM + i] = __float2bfloat16(xr[i] * sc * w[i]);
}

// ---------------- causal depthwise conv (K=4) + bias + SiLU -> bf16 ---------
__global__ void conv_silu_k(const float* __restrict__ cw, const float* __restrict__ cb)
{
    int c = blockIdx.x * 256 + threadIdx.x;
    int t = blockIdx.y;
    int b = blockIdx.z;
    float4 w = ((const float4*)cw)[c];
    float acc = cb[c];
    size_t colbase = (size_t)b * TT * (2 * DI) + c;
    const size_t stride = 2 * DI;
    if (t >= 3) acc += w.x * g_xz[colbase + (size_t)(t - 3) * stride];
    if (t >= 2) acc += w.y * g_xz[colbase + (size_t)(t - 2) * stride];
    if (t >= 1) acc += w.z * g_xz[colbase + (size_t)(t - 1) * stride];
    acc += w.w * g_xz[colbase + (size_t)t * stride];
    float sig = 1.f / (1.f + expf(-acc));
    g_xs[((size_t)b * TT + t) * DI + c] = __float2bfloat16(acc * sig);
}

// ---------------- dt finalize: softplus(raw + bias) -------------------------
__global__ void dt_fin_k(const float* __restrict__ dtb)
{
    int i = blockIdx.x * 256 + threadIdx.x;
    if (i < NROWS * NH) {
        int row = i >> 3, h = i & 7;
        float v = g_bcdt[(size_t)row * NCATP + 1024 + h] + dtb[h];
        g_dt[i] = (v > 20.f) ? v : log1pf(expf(v));
    }
}

// ---------------- selective scan v2: smem-staged chunks ---------------------
#define SCH 32
#define NCHUNK (TT / SCH)    // 64

__global__ void __launch_bounds__(256)
scan_k(const float* __restrict__ A_log, const float* __restrict__ Dp)
{
    __shared__ float Bs[2][SCH][64];
    __shared__ float Cs[2][SCH][64];
    __shared__ float Zs[2][SCH][32];
    __shared__ __nv_bfloat16 Xs[2][SCH][32];
    __shared__ float Dts[2][SCH];

    int tid = threadIdx.x;
    int dtile = blockIdx.x;
    int h = blockIdx.y;
    int b = blockIdx.z;
    int warp = tid >> 5, lane = tid & 31;
    int dl = lane & 3;
    int ng = lane >> 2;                 // 0..7
    int li = warp * 4 + dl;             // 0..31 local d index
    int d = dtile * 32 + li;
    int nbase = ng * 8;

    size_t rb = (size_t)b * TT;
    int xoff = h * DH + d;

    auto load_chunk = [&](int c) {
        int bb = c & 1;
        size_t t0 = rb + (size_t)c * SCH;
        const float* bsrc = g_bcdt + t0 * NCATP + h * 64;
        const float* csrc = bsrc + 512;
        const float* zsrc = g_xz + t0 * (2 * DI) + DI + h * DH + dtile * 32;
        const __nv_bfloat16* xsrc = g_xs + t0 * DI + h * DH + dtile * 32;
        for (int i = tid; i < 1408; i += 256) {
            if (i < 512) {
                int tl = i >> 4, p = i & 15;
                CP_ASYNC16(smem_u32(&Bs[bb][tl][p * 4]), bsrc + (size_t)tl * NCATP + p * 4);
            } else if (i < 1024) {
                int tl = (i - 512) >> 4, p = (i - 512) & 15;
                CP_ASYNC16(smem_u32(&Cs[bb][tl][p * 4]), csrc + (size_t)tl * NCATP + p * 4);
            } else if (i < 1280) {
                int tl = (i - 1024) >> 3, p = (i - 1024) & 7;
                CP_ASYNC16(smem_u32(&Zs[bb][tl][p * 4]), zsrc + (size_t)tl * (2 * DI) + p * 4);
            } else {
                int tl = (i - 1280) >> 2, p = (i - 1280) & 3;
                CP_ASYNC16(smem_u32(&Xs[bb][tl][p * 8]), xsrc + (size_t)tl * DI + p * 8);
            }
        }
        if (tid < SCH)
            CP_ASYNC4(smem_u32(&Dts[bb][tid]), g_dt + (t0 + tid) * NH + h);
    };

    float A = -expf(A_log[h]);
    float Dh = Dp[h];
    float hs[8];
    #pragma unroll
    for (int j = 0; j < 8; j++) hs[j] = 0.f;

    load_chunk(0); CP_COMMIT();

    for (int c = 0; c < NCHUNK; c++) {
        if (c + 1 < NCHUNK) load_chunk(c + 1);
        CP_COMMIT();
        CP_WAIT1();
        __syncthreads();

        int bb = c & 1;
        size_t orow = rb + (size_t)c * SCH;
        #pragma unroll 4
        for (int tl = 0; tl < SCH; tl++) {
            float dtv = Dts[bb][tl];
            float4 b0 = *(const float4*)&Bs[bb][tl][nbase];
            float4 b1 = *(const float4*)&Bs[bb][tl][nbase + 4];
            float4 c0 = *(const float4*)&Cs[bb][tl][nbase];
            float4 c1 = *(const float4*)&Cs[bb][tl][nbase + 4];
            float xd = __bfloat162float(Xs[bb][tl][li]);

            float dA = __expf(dtv * A);
            float dtx = dtv * xd;
            float acc;
            hs[0] = dA * hs[0] + b0.x * dtx; acc  = c0.x * hs[0];
            hs[1] = dA * hs[1] + b0.y * dtx; acc += c0.y * hs[1];
            hs[2] = dA * hs[2] + b0.z * dtx; acc += c0.z * hs[2];
            hs[3] = dA * hs[3] + b0.w * dtx; acc += c0.w * hs[3];
            hs[4] = dA * hs[4] + b1.x * dtx; acc += c1.x * hs[4];
            hs[5] = dA * hs[5] + b1.y * dtx; acc += c1.y * hs[5];
            hs[6] = dA * hs[6] + b1.z * dtx; acc += c1.z * hs[6];
            hs[7] = dA * hs[7] + b1.w * dtx; acc += c1.w * hs[7];

            acc += __shfl_xor_sync(0xffffffffu, acc, 16);
            acc += __shfl_xor_sync(0xffffffffu, acc, 8);
            acc += __shfl_xor_sync(0xffffffffu, acc, 4);

            if (ng == 0) {
                float zv = Zs[bb][tl][li];
                float sig = 1.f / (1.f + __expf(-zv));
                g_y[(orow + tl) * DI + xoff] = __float2bfloat16((acc + Dh * xd) * (zv * sig));
            }
        }
        __syncthreads();
    }
}

// ---------------- launch ----------------------------------------------------
extern "C" void kernel_launch(void* const* d_in, const int* in_sizes, int n_in,
                              void* d_out, int out_size)
{
    const float* x      = (const float*)d_in[0];
    const float* norm_w = (const float*)d_in[1];
    const float* in_w   = (const float*)d_in[2];
    const float* conv_w = (const float*)d_in[3];
    const float* conv_b = (const float*)d_in[4];
    const float* A_log  = (const float*)d_in[5];
    const float* B_w    = (const float*)d_in[6];
    const float* C_w    = (const float*)d_in[7];
    const float* dt_w   = (const float*)d_in[8];
    const float* dt_b   = (const float*)d_in[9];
    const float* Dp     = (const float*)d_in[10];
    const float* out_w  = (const float*)d_in[11];
    float* out = (float*)d_out;

    __nv_bfloat16 *p_xn, *p_xs, *p_y, *p_inw, *p_wcat, *p_outw;
    float *p_xz, *p_bcdt;
    cudaGetSymbolAddress((void**)&p_xn, g_xn);
    cudaGetSymbolAddress((void**)&p_xz, g_xz);
    cudaGetSymbolAddress((void**)&p_xs, g_xs);
    cudaGetSymbolAddress((void**)&p_bcdt, g_bcdt);
    cudaGetSymbolAddress((void**)&p_y, g_y);
    cudaGetSymbolAddress((void**)&p_inw, g_inw);
    cudaGetSymbolAddress((void**)&p_wcat, g_wcat);
    cudaGetSymbolAddress((void**)&p_outw, g_outw);

    cudaFuncSetAttribute(gemm_mma<false>, cudaFuncAttributeMaxDynamicSharedMemorySize, GEMM_SMEM);
    cudaFuncSetAttribute(gemm_mma<true>,  cudaFuncAttributeMaxDynamicSharedMemorySize, GEMM_SMEM);

    // weight conversions (bf16)
    cvt_bf16_k<<<256, 256>>>(in_w, p_inw, 2 * DI * DM);
    cvt_bf16_k<<<256, 256>>>(out_w, p_outw, DM * DI);
    build_wcat_k<<<256, 256>>>(B_w, C_w, dt_w);

    // 1. RMSNorm -> bf16
    rmsnorm_k<<<NROWS, 256>>>(x, norm_w);

    // 2. xz = xn @ in_w^T   (4096 x 4096 x 1024)
    gemm_mma<false><<<dim3(4096 / BN, NROWS / BM), 128, GEMM_SMEM>>>(
        p_xn, p_inw, p_xz, nullptr, NROWS, 2 * DI, DM);

    // 3. causal conv + SiLU -> bf16
    conv_silu_k<<<dim3(DI / 256, TT, BSZ), 256>>>(conv_w, conv_b);

    // 4. [B | C | dt] = xs @ wcat^T   (4096 x 1152 x 2048)
    gemm_mma<false><<<dim3(NCATP / BN, NROWS / BM), 128, GEMM_SMEM>>>(
        p_xs, p_wcat, p_bcdt, nullptr, NROWS, NCATP, DI);

    // 5. dt softplus
    dt_fin_k<<<(NROWS * NH + 255) / 256, 256>>>(dt_b);

    // 6. selective scan + gating -> bf16 (smem-staged)
    scan_k<<<dim3(8, NH, BSZ), 256>>>(A_log, Dp);

    // 7. out = y @ out_w^T + residual   (4096 x 1024 x 2048)
    gemm_mma<true><<<dim3(1024 / BN, NROWS / BM), 128, GEMM_SMEM>>>(
        p_y, p_outw, out, x, NROWS, DM, DI);
}

// round 9
// speedup vs baseline: 1.0831x; 1.0831x over previous
#include <cuda_runtime.h>
#include <cuda_bf16.h>
#include <math.h>
#include <stdint.h>

// ---------------- problem constants ----------------------------------------
#define BSZ 2
#define TT 2048
#define DM 1024
#define DI 2048
#define NH 8
#define DS 64
#define DH 256
#define NROWS (BSZ*TT)          // 4096
#define EPSV 1e-6f
#define NCATP 1152              // B(512) | C(512) | dt(8) | pad -> 9*128

// ---------------- scratch (device globals) ---------------------------------
__device__ __nv_bfloat16 g_xn[(size_t)NROWS * DM];
__device__ float         g_xz[(size_t)NROWS * 2 * DI];
__device__ __nv_bfloat16 g_xs[(size_t)NROWS * DI];
__device__ float         g_bcdt[(size_t)NROWS * NCATP];
__device__ float         g_dt[(size_t)NROWS * NH];
__device__ __nv_bfloat16 g_y [(size_t)NROWS * DI];
__device__ __nv_bfloat16 g_inw [(size_t)(2*DI) * DM];
__device__ __nv_bfloat16 g_wcat[(size_t)NCATP * DI];
__device__ __nv_bfloat16 g_outw[(size_t)DM * DI];

// ---------------- PTX helpers ----------------------------------------------
__device__ __forceinline__ uint32_t smem_u32(const void* p) {
    uint32_t a;
    asm("{ .reg .u64 t; cvta.to.shared.u64 t, %1; cvt.u32.u64 %0, t; }" : "=r"(a) : "l"(p));
    return a;
}

#define CP_ASYNC16(dst, src) \
    asm volatile("cp.async.cg.shared.global [%0], [%1], 16;" :: "r"(dst), "l"(src) : "memory")
#define CP_ASYNC4(dst, src) \
    asm volatile("cp.async.ca.shared.global [%0], [%1], 4;" :: "r"(dst), "l"(src) : "memory")
#define CP_COMMIT() asm volatile("cp.async.commit_group;" ::: "memory")
#define CP_WAIT1()  asm volatile("cp.async.wait_group 1;" ::: "memory")

#define LDM_X4(r0, r1, r2, r3, addr) \
    asm volatile("ldmatrix.sync.aligned.m8n8.x4.shared.b16 {%0,%1,%2,%3}, [%4];" \
                 : "=r"(r0), "=r"(r1), "=r"(r2), "=r"(r3) : "r"(addr))
#define LDM_X2(r0, r1, addr) \
    asm volatile("ldmatrix.sync.aligned.m8n8.x2.shared.b16 {%0,%1}, [%2];" \
                 : "=r"(r0), "=r"(r1) : "r"(addr))

#define MMA16816(d, a0, a1, a2, a3, b0, b1) \
    asm volatile("mma.sync.aligned.m16n8k16.row.col.f32.bf16.bf16.f32 " \
                 "{%0,%1,%2,%3}, {%4,%5,%6,%7}, {%8,%9}, {%0,%1,%2,%3};" \
                 : "+f"((d)[0]), "+f"((d)[1]), "+f"((d)[2]), "+f"((d)[3]) \
                 : "r"(a0), "r"(a1), "r"(a2), "r"(a3), "r"(b0), "r"(b1))

// ---------------- bf16 mma.sync GEMM: C[M,N] = A[M,K] @ W[N,K]^T (+Res) ----
// BM=BN=128, BK=64, 3-stage cp.async ring, 256 threads, 8 warps (2x4),
// warp tile 64x32. One __syncthreads per K-tile; loads overlap compute.
#define BM 128
#define BN 128
#define BK64 64
#define ROWB 144                         // 64*2 + 16 pad bytes
#define SA_BYTES (BM * ROWB)             // 18432
#define STG_BYTES (2 * SA_BYTES)         // 36864 (A + B)
#define NST 3
#define GEMM_SMEM (NST * STG_BYTES)      // 110592

template <bool ADD_RES>
__global__ void __launch_bounds__(256)
gemm_mma(const __nv_bfloat16* __restrict__ A, const __nv_bfloat16* __restrict__ W,
         float* __restrict__ C, const float* __restrict__ Res,
         int M, int N, int K)
{
    extern __shared__ char sm[];
    uint32_t base = smem_u32(sm);

    int tid = threadIdx.x;
    int wid = tid >> 5, lane = tid & 31;
    int wm = wid >> 2, wn = wid & 3;          // 2 x 4 warp grid, tile 64x32
    int m0 = blockIdx.y * BM;
    int n0 = blockIdx.x * BN;

    const __nv_bfloat16* Ag = A + (size_t)m0 * K;
    const __nv_bfloat16* Wg = W + (size_t)n0 * K;

    float acc[4][4][4];
    #pragma unroll
    for (int i = 0; i < 4; i++)
        #pragma unroll
        for (int j = 0; j < 4; j++)
            #pragma unroll
            for (int f = 0; f < 4; f++) acc[i][j][f] = 0.f;

    int nk = K / BK64;

    // stage loader: A and B each 128 rows x 8 16B-chunks = 1024 chunks
    auto load_stage = [&](int s, int k0) {
        uint32_t sA = base + s * STG_BYTES;
        uint32_t sB = sA + SA_BYTES;
        #pragma unroll
        for (int it = 0; it < 4; it++) {
            int i = tid + it * 256;
            int r = i >> 3, c = i & 7;
            CP_ASYNC16(sA + r * ROWB + c * 16, Ag + (size_t)r * K + k0 + c * 8);
        }
        #pragma unroll
        for (int it = 0; it < 4; it++) {
            int i = tid + it * 256;
            int r = i >> 3, c = i & 7;
            CP_ASYNC16(sB + r * ROWB + c * 16, Wg + (size_t)r * K + k0 + c * 8);
        }
    };

    load_stage(0, 0);      CP_COMMIT();
    load_stage(1, BK64);   CP_COMMIT();

    int stg = 0;                      // stage index of tile kt (mod 3)
    for (int kt = 0; kt < nk; kt++) {
        CP_WAIT1();                   // stage kt complete
        __syncthreads();

        // issue loads for tile kt+2 (overlaps with compute below)
        int s2 = stg + 2; if (s2 >= NST) s2 -= NST;
        if (kt + 2 < nk) load_stage(s2, (kt + 2) * BK64);
        CP_COMMIT();                  // always commit (group accounting)

        uint32_t sA = base + stg * STG_BYTES;
        uint32_t sB = sA + SA_BYTES;

        #pragma unroll
        for (int ks = 0; ks < 4; ks++) {
            int colA = ks * 32 + (lane >> 4) * 16;           // bytes
            int colB = ks * 32 + ((lane >> 3) & 1) * 16;     // bytes
            uint32_t a[4][4], b[4][2];
            #pragma unroll
            for (int i = 0; i < 4; i++) {
                int row = wm * 64 + i * 16 + (lane & 15);
                LDM_X4(a[i][0], a[i][1], a[i][2], a[i][3],
                       sA + (uint32_t)(row * ROWB + colA));
            }
            #pragma unroll
            for (int j = 0; j < 4; j++) {
                int row = wn * 32 + j * 8 + (lane & 7);
                LDM_X2(b[j][0], b[j][1],
                       sB + (uint32_t)(row * ROWB + colB));
            }
            #pragma unroll
            for (int i = 0; i < 4; i++)
                #pragma unroll
                for (int j = 0; j < 4; j++)
                    MMA16816(acc[i][j], a[i][0], a[i][1], a[i][2], a[i][3],
                             b[j][0], b[j][1]);
        }
        stg++; if (stg >= NST) stg -= NST;
    }

    // epilogue: direct register -> gmem (float2 per c-frag half)
    int gid = lane >> 2, t4 = lane & 3;
    #pragma unroll
    for (int i = 0; i < 4; i++) {
        int row0 = m0 + wm * 64 + i * 16 + gid;
        #pragma unroll
        for (int j = 0; j < 4; j++) {
            int col = n0 + wn * 32 + j * 8 + t4 * 2;
            size_t i0 = (size_t)row0 * N + col;
            size_t i1 = (size_t)(row0 + 8) * N + col;
            float2 v0 = make_float2(acc[i][j][0], acc[i][j][1]);
            float2 v1 = make_float2(acc[i][j][2], acc[i][j][3]);
            if (ADD_RES) {
                float2 r0 = *(const float2*)(Res + i0);
                float2 r1 = *(const float2*)(Res + i1);
                v0.x += r0.x; v0.y += r0.y;
                v1.x += r1.x; v1.y += r1.y;
            }
            *(float2*)(C + i0) = v0;
            *(float2*)(C + i1) = v1;
        }
    }
}

// ---------------- weight conversion ----------------------------------------
__global__ void cvt_bf16_k(const float* __restrict__ in, __nv_bfloat16* __restrict__ out, int n)
{
    for (int i = blockIdx.x * 256 + threadIdx.x; i < n; i += gridDim.x * 256)
        out[i] = __float2bfloat16(in[i]);
}

__global__ void build_wcat_k(const float* __restrict__ Bw, const float* __restrict__ Cw,
                             const float* __restrict__ dtw)
{
    int n = NCATP * DI;
    for (int i = blockIdx.x * 256 + threadIdx.x; i < n; i += gridDim.x * 256) {
        int r = i >> 11, k = i & (DI - 1);
        float v;
        if (r < 512)       v = Bw[(size_t)r * DI + k];
        else if (r < 1024) v = Cw[(size_t)(r - 512) * DI + k];
        else if (r < 1032) v = dtw[(size_t)(r - 1024) * DI + k];
        else               v = 0.f;
        g_wcat[i] = __float2bfloat16(v);
    }
}

// ---------------- RMSNorm (writes bf16) -------------------------------------
__global__ void rmsnorm_k(const float* __restrict__ x, const float* __restrict__ w)
{
    int row = blockIdx.x;
    const float* xr = x + (size_t)row * DM;
    float s = 0.f;
    for (int i = threadIdx.x; i < DM; i += 256) { float v = xr[i]; s += v * v; }
    __shared__ float red[8];
    #pragma unroll
    for (int o = 16; o; o >>= 1) s += __shfl_xor_sync(0xffffffffu, s, o);
    if ((threadIdx.x & 31) == 0) red[threadIdx.x >> 5] = s;
    __syncthreads();
    if (threadIdx.x < 8) {
        float v = red[threadIdx.x];
        #pragma unroll
        for (int o = 4; o; o >>= 1) v += __shfl_xor_sync(0xffu, v, o);
        if (threadIdx.x == 0) red[0] = rsqrtf(v / (float)DM + EPSV);
    }
    __syncthreads();
    float sc = red[0];
    for (int i = threadIdx.x; i < DM; i += 256)
        g_xn[(size_t)row * DM + i] = __float2bfloat16(xr[i] * sc * w[i]);
}

// ---------------- causal depthwise conv (K=4) + bias + SiLU -> bf16 ---------
// each thread computes 4 consecutive timesteps for one channel (7 loads / 4 outs)
__global__ void conv_silu_k(const float* __restrict__ cw, const float* __restrict__ cb)
{
    int c = blockIdx.x * 256 + threadIdx.x;   // 0..2047
    int t0 = blockIdx.y * 4;                  // 0,4,...,2044
    int b = blockIdx.z;
    float4 w = ((const float4*)cw)[c];
    float bias = cb[c];
    size_t colbase = (size_t)b * TT * (2 * DI) + c;
    const size_t stride = 2 * DI;

    float xv[7];
    #pragma unroll
    for (int k = 0; k < 7; k++) {
        int t = t0 - 3 + k;
        xv[k] = (t >= 0) ? g_xz[colbase + (size_t)t * stride] : 0.f;
    }
    size_t obase = ((size_t)b * TT + t0) * DI + c;
    #pragma unroll
    for (int i = 0; i < 4; i++) {
        float acc = bias + w.x * xv[i] + w.y * xv[i + 1] + w.z * xv[i + 2] + w.w * xv[i + 3];
        float sig = 1.f / (1.f + __expf(-acc));
        g_xs[obase + (size_t)i * DI] = __float2bfloat16(acc * sig);
    }
}

// ---------------- dt finalize: softplus(raw + bias) -------------------------
__global__ void dt_fin_k(const float* __restrict__ dtb)
{
    int i = blockIdx.x * 256 + threadIdx.x;
    if (i < NROWS * NH) {
        int row = i >> 3, h = i & 7;
        float v = g_bcdt[(size_t)row * NCATP + 1024 + h] + dtb[h];
        g_dt[i] = (v > 20.f) ? v : log1pf(expf(v));
    }
}

// ---------------- selective scan v2: smem-staged chunks ---------------------
#define SCH 32
#define NCHUNK (TT / SCH)    // 64

__global__ void __launch_bounds__(256)
scan_k(const float* __restrict__ A_log, const float* __restrict__ Dp)
{
    __shared__ float Bs[2][SCH][64];
    __shared__ float Cs[2][SCH][64];
    __shared__ float Zs[2][SCH][32];
    __shared__ __nv_bfloat16 Xs[2][SCH][32];
    __shared__ float Dts[2][SCH];

    int tid = threadIdx.x;
    int dtile = blockIdx.x;
    int h = blockIdx.y;
    int b = blockIdx.z;
    int warp = tid >> 5, lane = tid & 31;
    int dl = lane & 3;
    int ng = lane >> 2;                 // 0..7
    int li = warp * 4 + dl;             // 0..31 local d index
    int d = dtile * 32 + li;
    int nbase = ng * 8;

    size_t rb = (size_t)b * TT;
    int xoff = h * DH + d;

    auto load_chunk = [&](int c) {
        int bb = c & 1;
        size_t t0 = rb + (size_t)c * SCH;
        const float* bsrc = g_bcdt + t0 * NCATP + h * 64;
        const float* csrc = bsrc + 512;
        const float* zsrc = g_xz + t0 * (2 * DI) + DI + h * DH + dtile * 32;
        const __nv_bfloat16* xsrc = g_xs + t0 * DI + h * DH + dtile * 32;
        for (int i = tid; i < 1408; i += 256) {
            if (i < 512) {
                int tl = i >> 4, p = i & 15;
                CP_ASYNC16(smem_u32(&Bs[bb][tl][p * 4]), bsrc + (size_t)tl * NCATP + p * 4);
            } else if (i < 1024) {
                int tl = (i - 512) >> 4, p = (i - 512) & 15;
                CP_ASYNC16(smem_u32(&Cs[bb][tl][p * 4]), csrc + (size_t)tl * NCATP + p * 4);
            } else if (i < 1280) {
                int tl = (i - 1024) >> 3, p = (i - 1024) & 7;
                CP_ASYNC16(smem_u32(&Zs[bb][tl][p * 4]), zsrc + (size_t)tl * (2 * DI) + p * 4);
            } else {
                int tl = (i - 1280) >> 2, p = (i - 1280) & 3;
                CP_ASYNC16(smem_u32(&Xs[bb][tl][p * 8]), xsrc + (size_t)tl * DI + p * 8);
            }
        }
        if (tid < SCH)
            CP_ASYNC4(smem_u32(&Dts[bb][tid]), g_dt + (t0 + tid) * NH + h);
    };

    float A = -expf(A_log[h]);
    float Dh = Dp[h];
    float hs[8];
    #pragma unroll
    for (int j = 0; j < 8; j++) hs[j] = 0.f;

    load_chunk(0); CP_COMMIT();

    for (int c = 0; c < NCHUNK; c++) {
        if (c + 1 < NCHUNK) load_chunk(c + 1);
        CP_COMMIT();
        CP_WAIT1();
        __syncthreads();

        int bb = c & 1;
        size_t orow = rb + (size_t)c * SCH;
        #pragma unroll 4
        for (int tl = 0; tl < SCH; tl++) {
            float dtv = Dts[bb][tl];
            float4 b0 = *(const float4*)&Bs[bb][tl][nbase];
            float4 b1 = *(const float4*)&Bs[bb][tl][nbase + 4];
            float4 c0 = *(const float4*)&Cs[bb][tl][nbase];
            float4 c1 = *(const float4*)&Cs[bb][tl][nbase + 4];
            float xd = __bfloat162float(Xs[bb][tl][li]);

            float dA = __expf(dtv * A);
            float dtx = dtv * xd;
            float acc;
            hs[0] = dA * hs[0] + b0.x * dtx; acc  = c0.x * hs[0];
            hs[1] = dA * hs[1] + b0.y * dtx; acc += c0.y * hs[1];
            hs[2] = dA * hs[2] + b0.z * dtx; acc += c0.z * hs[2];
            hs[3] = dA * hs[3] + b0.w * dtx; acc += c0.w * hs[3];
            hs[4] = dA * hs[4] + b1.x * dtx; acc += c1.x * hs[4];
            hs[5] = dA * hs[5] + b1.y * dtx; acc += c1.y * hs[5];
            hs[6] = dA * hs[6] + b1.z * dtx; acc += c1.z * hs[6];
            hs[7] = dA * hs[7] + b1.w * dtx; acc += c1.w * hs[7];

            acc += __shfl_xor_sync(0xffffffffu, acc, 16);
            acc += __shfl_xor_sync(0xffffffffu, acc, 8);
            acc += __shfl_xor_sync(0xffffffffu, acc, 4);

            if (ng == 0) {
                float zv = Zs[bb][tl][li];
                float sig = 1.f / (1.f + __expf(-zv));
                g_y[(orow + tl) * DI + xoff] = __float2bfloat16((acc + Dh * xd) * (zv * sig));
            }
        }
        __syncthreads();
    }
}

// ---------------- launch ----------------------------------------------------
extern "C" void kernel_launch(void* const* d_in, const int* in_sizes, int n_in,
                              void* d_out, int out_size)
{
    const float* x      = (const float*)d_in[0];
    const float* norm_w = (const float*)d_in[1];
    const float* in_w   = (const float*)d_in[2];
    const float* conv_w = (const float*)d_in[3];
    const float* conv_b = (const float*)d_in[4];
    const float* A_log  = (const float*)d_in[5];
    const float* B_w    = (const float*)d_in[6];
    const float* C_w    = (const float*)d_in[7];
    const float* dt_w   = (const float*)d_in[8];
    const float* dt_b   = (const float*)d_in[9];
    const float* Dp     = (const float*)d_in[10];
    const float* out_w  = (const float*)d_in[11];
    float* out = (float*)d_out;

    __nv_bfloat16 *p_xn, *p_xs, *p_y, *p_inw, *p_wcat, *p_outw;
    float *p_xz, *p_bcdt;
    cudaGetSymbolAddress((void**)&p_xn, g_xn);
    cudaGetSymbolAddress((void**)&p_xz, g_xz);
    cudaGetSymbolAddress((void**)&p_xs, g_xs);
    cudaGetSymbolAddress((void**)&p_bcdt, g_bcdt);
    cudaGetSymbolAddress((void**)&p_y, g_y);
    cudaGetSymbolAddress((void**)&p_inw, g_inw);
    cudaGetSymbolAddress((void**)&p_wcat, g_wcat);
    cudaGetSymbolAddress((void**)&p_outw, g_outw);

    cudaFuncSetAttribute(gemm_mma<false>, cudaFuncAttributeMaxDynamicSharedMemorySize, GEMM_SMEM);
    cudaFuncSetAttribute(gemm_mma<true>,  cudaFuncAttributeMaxDynamicSharedMemorySize, GEMM_SMEM);

    // order arranged so the in-proj GEMM lands on the ncu capture slot
    // [0] in_w -> bf16
    cvt_bf16_k<<<256, 256>>>(in_w, p_inw, 2 * DI * DM);
    // [1] RMSNorm -> bf16
    rmsnorm_k<<<NROWS, 256>>>(x, norm_w);
    // [2] out_w -> bf16
    cvt_bf16_k<<<256, 256>>>(out_w, p_outw, DM * DI);
    // [3] xz = xn @ in_w^T   (4096 x 4096 x 1024)
    gemm_mma<false><<<dim3(4096 / BN, NROWS / BM), 256, GEMM_SMEM>>>(
        p_xn, p_inw, p_xz, nullptr, NROWS, 2 * DI, DM);
    // [4] fused [B|C|dt] weight
    build_wcat_k<<<256, 256>>>(B_w, C_w, dt_w);
    // [5] causal conv + SiLU -> bf16
    conv_silu_k<<<dim3(DI / 256, TT / 4, BSZ), 256>>>(conv_w, conv_b);
    // [6] [B | C | dt] = xs @ wcat^T   (4096 x 1152 x 2048)
    gemm_mma<false><<<dim3(NCATP / BN, NROWS / BM), 256, GEMM_SMEM>>>(
        p_xs, p_wcat, p_bcdt, nullptr, NROWS, NCATP, DI);
    // [7] dt softplus
    dt_fin_k<<<(NROWS * NH + 255) / 256, 256>>>(dt_b);
    // [8] selective scan + gating -> bf16 (smem-staged)
    scan_k<<<dim3(8, NH, BSZ), 256>>>(A_log, Dp);
    // [9] out = y @ out_w^T + residual   (4096 x 1024 x 2048)
    gemm_mma<true><<<dim3(1024 / BN, NROWS / BM), 256, GEMM_SMEM>>>(
        p_y, p_outw, out, x, NROWS, DM, DI);
}

// round 10
// speedup vs baseline: 2.1478x; 1.9830x over previous
#include <cuda_runtime.h>
#include <cuda_bf16.h>
#include <math.h>
#include <stdint.h>

// ---------------- problem constants ----------------------------------------
#define BSZ 2
#define TT 2048
#define DM 1024
#define DI 2048
#define NH 8
#define DS 64
#define DH 256
#define NROWS (BSZ*TT)          // 4096
#define EPSV 1e-6f
#define NCATP 1152              // B(512) | C(512) | dt(8) | pad -> 9*128
#define CHK 64
#define NCHKS (TT/CHK)          // 32

// ---------------- scratch (device globals) ---------------------------------
__device__ __nv_bfloat16 g_xn[(size_t)NROWS * DM];
__device__ float         g_xz[(size_t)NROWS * 2 * DI];
__device__ __nv_bfloat16 g_xs[(size_t)NROWS * DI];
__device__ __nv_bfloat16 g_bcdt[(size_t)NROWS * NCATP];
__device__ float         g_dt[(size_t)NROWS * NH];
__device__ __nv_bfloat16 g_y [(size_t)NROWS * DI];
__device__ float         g_yi[(size_t)NROWS * DI];                 // Y_intra fp32
__device__ float         g_hc [(size_t)16 * NCHKS * DS * DH];      // chunk state contribs
__device__ __nv_bfloat16 g_hin[(size_t)16 * NCHKS * DS * DH];      // per-chunk incoming state
__device__ float         g_S  [(size_t)16 * TT];                   // in-chunk cumsum of dt*A
__device__ __nv_bfloat16 g_inw [(size_t)(2*DI) * DM];
__device__ __nv_bfloat16 g_wcat[(size_t)NCATP * DI];
__device__ __nv_bfloat16 g_outw[(size_t)DM * DI];

// ---------------- PTX helpers ----------------------------------------------
__device__ __forceinline__ uint32_t smem_u32(const void* p) {
    uint32_t a;
    asm("{ .reg .u64 t; cvta.to.shared.u64 t, %1; cvt.u32.u64 %0, t; }" : "=r"(a) : "l"(p));
    return a;
}

#define CP_ASYNC16(dst, src) \
    asm volatile("cp.async.cg.shared.global [%0], [%1], 16;" :: "r"(dst), "l"(src) : "memory")
#define CP_ASYNC4(dst, src) \
    asm volatile("cp.async.ca.shared.global [%0], [%1], 4;" :: "r"(dst), "l"(src) : "memory")
#define CP_COMMIT() asm volatile("cp.async.commit_group;" ::: "memory")
#define CP_WAIT1()  asm volatile("cp.async.wait_group 1;" ::: "memory")
#define CP_WAIT0()  asm volatile("cp.async.wait_group 0;" ::: "memory")

#define LDM_X4(r0, r1, r2, r3, addr) \
    asm volatile("ldmatrix.sync.aligned.m8n8.x4.shared.b16 {%0,%1,%2,%3}, [%4];" \
                 : "=r"(r0), "=r"(r1), "=r"(r2), "=r"(r3) : "r"(addr))
#define LDM_X4T(r0, r1, r2, r3, addr) \
    asm volatile("ldmatrix.sync.aligned.m8n8.x4.trans.shared.b16 {%0,%1,%2,%3}, [%4];" \
                 : "=r"(r0), "=r"(r1), "=r"(r2), "=r"(r3) : "r"(addr))
#define LDM_X2(r0, r1, addr) \
    asm volatile("ldmatrix.sync.aligned.m8n8.x2.shared.b16 {%0,%1}, [%2];" \
                 : "=r"(r0), "=r"(r1) : "r"(addr))

#define MMA16816(d, a0, a1, a2, a3, b0, b1) \
    asm volatile("mma.sync.aligned.m16n8k16.row.col.f32.bf16.bf16.f32 " \
                 "{%0,%1,%2,%3}, {%4,%5,%6,%7}, {%8,%9}, {%0,%1,%2,%3};" \
                 : "+f"((d)[0]), "+f"((d)[1]), "+f"((d)[2]), "+f"((d)[3]) \
                 : "r"(a0), "r"(a1), "r"(a2), "r"(a3), "r"(b0), "r"(b1))

// ---------------- bf16 mma.sync GEMM: C[M,N] = A[M,K] @ W[N,K]^T (+Res) ----
// BM=BN=128, BK=64, 3-stage cp.async ring, 256 threads, 8 warps (2x4),
// warp tile 64x32.
#define BM 128
#define BN 128
#define BK64 64
#define ROWB 144
#define SA_BYTES (BM * ROWB)
#define STG_BYTES (2 * SA_BYTES)
#define NST 3
#define GEMM_SMEM (NST * STG_BYTES)      // 110592

template <bool ADD_RES, bool OUT_BF16>
__global__ void __launch_bounds__(256)
gemm_mma(const __nv_bfloat16* __restrict__ A, const __nv_bfloat16* __restrict__ W,
         void* __restrict__ Cout, const float* __restrict__ Res,
         int M, int N, int K)
{
    extern __shared__ char sm[];
    uint32_t base = smem_u32(sm);

    int tid = threadIdx.x;
    int wid = tid >> 5, lane = tid & 31;
    int wm = wid >> 2, wn = wid & 3;
    int m0 = blockIdx.y * BM;
    int n0 = blockIdx.x * BN;

    const __nv_bfloat16* Ag = A + (size_t)m0 * K;
    const __nv_bfloat16* Wg = W + (size_t)n0 * K;

    float acc[4][4][4];
    #pragma unroll
    for (int i = 0; i < 4; i++)
        #pragma unroll
        for (int j = 0; j < 4; j++)
            #pragma unroll
            for (int f = 0; f < 4; f++) acc[i][j][f] = 0.f;

    int nk = K / BK64;

    auto load_stage = [&](int s, int k0) {
        uint32_t sA = base + s * STG_BYTES;
        uint32_t sB = sA + SA_BYTES;
        #pragma unroll
        for (int it = 0; it < 4; it++) {
            int i = tid + it * 256;
            int r = i >> 3, c = i & 7;
            CP_ASYNC16(sA + r * ROWB + c * 16, Ag + (size_t)r * K + k0 + c * 8);
        }
        #pragma unroll
        for (int it = 0; it < 4; it++) {
            int i = tid + it * 256;
            int r = i >> 3, c = i & 7;
            CP_ASYNC16(sB + r * ROWB + c * 16, Wg + (size_t)r * K + k0 + c * 8);
        }
    };

    load_stage(0, 0);      CP_COMMIT();
    load_stage(1, BK64);   CP_COMMIT();

    int stg = 0;
    for (int kt = 0; kt < nk; kt++) {
        CP_WAIT1();
        __syncthreads();

        int s2 = stg + 2; if (s2 >= NST) s2 -= NST;
        if (kt + 2 < nk) load_stage(s2, (kt + 2) * BK64);
        CP_COMMIT();

        uint32_t sA = base + stg * STG_BYTES;
        uint32_t sB = sA + SA_BYTES;

        #pragma unroll
        for (int ks = 0; ks < 4; ks++) {
            int colA = ks * 32 + (lane >> 4) * 16;
            int colB = ks * 32 + ((lane >> 3) & 1) * 16;
            uint32_t a[4][4], b[4][2];
            #pragma unroll
            for (int i = 0; i < 4; i++) {
                int row = wm * 64 + i * 16 + (lane & 15);
                LDM_X4(a[i][0], a[i][1], a[i][2], a[i][3],
                       sA + (uint32_t)(row * ROWB + colA));
            }
            #pragma unroll
            for (int j = 0; j < 4; j++) {
                int row = wn * 32 + j * 8 + (lane & 7);
                LDM_X2(b[j][0], b[j][1],
                       sB + (uint32_t)(row * ROWB + colB));
            }
            #pragma unroll
            for (int i = 0; i < 4; i++)
                #pragma unroll
                for (int j = 0; j < 4; j++)
                    MMA16816(acc[i][j], a[i][0], a[i][1], a[i][2], a[i][3],
                             b[j][0], b[j][1]);
        }
        stg++; if (stg >= NST) stg -= NST;
    }

    int gid = lane >> 2, t4 = lane & 3;
    #pragma unroll
    for (int i = 0; i < 4; i++) {
        int row0 = m0 + wm * 64 + i * 16 + gid;
        #pragma unroll
        for (int j = 0; j < 4; j++) {
            int col = n0 + wn * 32 + j * 8 + t4 * 2;
            size_t i0 = (size_t)row0 * N + col;
            size_t i1 = (size_t)(row0 + 8) * N + col;
            float2 v0 = make_float2(acc[i][j][0], acc[i][j][1]);
            float2 v1 = make_float2(acc[i][j][2], acc[i][j][3]);
            if (ADD_RES) {
                float2 r0 = *(const float2*)(Res + i0);
                float2 r1 = *(const float2*)(Res + i1);
                v0.x += r0.x; v0.y += r0.y;
                v1.x += r1.x; v1.y += r1.y;
            }
            if (OUT_BF16) {
                __nv_bfloat16* Cb = (__nv_bfloat16*)Cout;
                __nv_bfloat162 o0, o1;
                o0.x = __float2bfloat16(v0.x); o0.y = __float2bfloat16(v0.y);
                o1.x = __float2bfloat16(v1.x); o1.y = __float2bfloat16(v1.y);
                *(__nv_bfloat162*)(Cb + i0) = o0;
                *(__nv_bfloat162*)(Cb + i1) = o1;
            } else {
                float* Cf = (float*)Cout;
                *(float2*)(Cf + i0) = v0;
                *(float2*)(Cf + i1) = v1;
            }
        }
    }
}

// ---------------- weight conversion ----------------------------------------
__global__ void cvt_bf16_k(const float* __restrict__ in, __nv_bfloat16* __restrict__ out, int n)
{
    for (int i = blockIdx.x * 256 + threadIdx.x; i < n; i += gridDim.x * 256)
        out[i] = __float2bfloat16(in[i]);
}

__global__ void build_wcat_k(const float* __restrict__ Bw, const float* __restrict__ Cw,
                             const float* __restrict__ dtw)
{
    int n = NCATP * DI;
    for (int i = blockIdx.x * 256 + threadIdx.x; i < n; i += gridDim.x * 256) {
        int r = i >> 11, k = i & (DI - 1);
        float v;
        if (r < 512)       v = Bw[(size_t)r * DI + k];
        else if (r < 1024) v = Cw[(size_t)(r - 512) * DI + k];
        else if (r < 1032) v = dtw[(size_t)(r - 1024) * DI + k];
        else               v = 0.f;
        g_wcat[i] = __float2bfloat16(v);
    }
}

// ---------------- RMSNorm (writes bf16) -------------------------------------
__global__ void rmsnorm_k(const float* __restrict__ x, const float* __restrict__ w)
{
    int row = blockIdx.x;
    const float* xr = x + (size_t)row * DM;
    float s = 0.f;
    for (int i = threadIdx.x; i < DM; i += 256) { float v = xr[i]; s += v * v; }
    __shared__ float red[8];
    #pragma unroll
    for (int o = 16; o; o >>= 1) s += __shfl_xor_sync(0xffffffffu, s, o);
    if ((threadIdx.x & 31) == 0) red[threadIdx.x >> 5] = s;
    __syncthreads();
    if (threadIdx.x < 8) {
        float v = red[threadIdx.x];
        #pragma unroll
        for (int o = 4; o; o >>= 1) v += __shfl_xor_sync(0xffu, v, o);
        if (threadIdx.x == 0) red[0] = rsqrtf(v / (float)DM + EPSV);
    }
    __syncthreads();
    float sc = red[0];
    for (int i = threadIdx.x; i < DM; i += 256)
        g_xn[(size_t)row * DM + i] = __float2bfloat16(xr[i] * sc * w[i]);
}

// ---------------- causal depthwise conv (K=4) + bias + SiLU -> bf16 ---------
__global__ void conv_silu_k(const float* __restrict__ cw, const float* __restrict__ cb)
{
    int c = blockIdx.x * 256 + threadIdx.x;
    int t0 = blockIdx.y * 4;
    int b = blockIdx.z;
    float4 w = ((const float4*)cw)[c];
    float bias = cb[c];
    size_t colbase = (size_t)b * TT * (2 * DI) + c;
    const size_t stride = 2 * DI;

    float xv[7];
    #pragma unroll
    for (int k = 0; k < 7; k++) {
        int t = t0 - 3 + k;
        xv[k] = (t >= 0) ? g_xz[colbase + (size_t)t * stride] : 0.f;
    }
    size_t obase = ((size_t)b * TT + t0) * DI + c;
    #pragma unroll
    for (int i = 0; i < 4; i++) {
        float acc = bias + w.x * xv[i] + w.y * xv[i + 1] + w.z * xv[i + 2] + w.w * xv[i + 3];
        float sig = 1.f / (1.f + __expf(-acc));
        g_xs[obase + (size_t)i * DI] = __float2bfloat16(acc * sig);
    }
}

// ---------------- dt finalize: softplus(raw + bias) -------------------------
__global__ void dt_fin_k(const float* __restrict__ dtb)
{
    int i = blockIdx.x * 256 + threadIdx.x;
    if (i < NROWS * NH) {
        int row = i >> 3, h = i & 7;
        float v = __bfloat162float(g_bcdt[(size_t)row * NCATP + 1024 + h]) + dtb[h];
        g_dt[i] = (v > 20.f) ? v : log1pf(expf(v));
    }
}

// ---------------- SSD phase A: intra-chunk + state contributions ------------
// One CTA per (chunk, h, b). 256 threads, 8 warps (2x4).
#define AO_C 0
#define AO_B 9216
#define AO_P 18432
#define AO_W 27648
#define AO_X 36864
#define AO_S 70656
#define AO_DT 70912
#define AO_WJ 71168
#define A_SMEM 71424

__global__ void __launch_bounds__(256)
chunk_intra_k(const float* __restrict__ A_log)
{
    extern __shared__ char sm[];
    uint32_t base = smem_u32(sm);
    float* S  = (float*)(sm + AO_S);
    float* DT = (float*)(sm + AO_DT);
    float* WJ = (float*)(sm + AO_WJ);

    int tid = threadIdx.x;
    int wid = tid >> 5, lane = tid & 31;
    int wm = wid >> 2, wn = wid & 3;
    int chunk = blockIdx.x, h = blockIdx.y, b = blockIdx.z;
    int bh = b * NH + h;
    size_t rowbase = (size_t)b * TT + (size_t)chunk * CHK;

    // loads: B, C (64x64 bf16 each), X (64x256 bf16), dt (64 fp32)
    const __nv_bfloat16* bsrc = g_bcdt + rowbase * NCATP + h * 64;
    for (int i = tid; i < 512; i += 256) {
        int r = i >> 3, c = i & 7;
        CP_ASYNC16(base + AO_B + r * 144 + c * 16, bsrc + (size_t)r * NCATP + c * 8);
        CP_ASYNC16(base + AO_C + r * 144 + c * 16, bsrc + (size_t)r * NCATP + 512 + c * 8);
    }
    for (int i = tid; i < 2048; i += 256) {
        int r = i >> 5, c = i & 31;
        CP_ASYNC16(base + AO_X + r * 528 + c * 16, g_xs + (rowbase + r) * DI + h * DH + c * 8);
    }
    if (tid < 64)
        CP_ASYNC4(base + AO_DT + tid * 4, g_dt + (rowbase + tid) * NH + h);
    CP_COMMIT();
    CP_WAIT0();
    __syncthreads();

    float Ah = -__expf(A_log[h]);
    // inclusive cumsum of a_t = dt_t * A (warp 0)
    if (wid == 0) {
        float a0 = DT[lane] * Ah, a1 = DT[lane + 32] * Ah;
        #pragma unroll
        for (int off = 1; off < 32; off <<= 1) {
            float u0 = __shfl_up_sync(0xffffffffu, a0, off);
            float u1 = __shfl_up_sync(0xffffffffu, a1, off);
            if (lane >= off) { a0 += u0; a1 += u1; }
        }
        float tot = __shfl_sync(0xffffffffu, a0, 31);
        a1 += tot;
        S[lane] = a0; S[lane + 32] = a1;
    }
    __syncthreads();
    if (tid < 64) WJ[tid] = __expf(S[63] - S[tid]) * DT[tid];

    // GEMM1: G = C @ B^T (64x64, K=64 over n)
    float acc1[2][2][4];
    #pragma unroll
    for (int i = 0; i < 2; i++)
        #pragma unroll
        for (int j = 0; j < 2; j++)
            #pragma unroll
            for (int f = 0; f < 4; f++) acc1[i][j][f] = 0.f;

    #pragma unroll
    for (int ks = 0; ks < 4; ks++) {
        uint32_t a[2][4], bb[4];
        #pragma unroll
        for (int i = 0; i < 2; i++) {
            int row = wm * 32 + i * 16 + (lane & 15);
            LDM_X4(a[i][0], a[i][1], a[i][2], a[i][3],
                   base + AO_C + (uint32_t)(row * 144 + ks * 32 + (lane >> 4) * 16));
        }
        {
            int row = wn * 16 + (lane & 15);
            LDM_X4(bb[0], bb[1], bb[2], bb[3],
                   base + AO_B + (uint32_t)(row * 144 + ks * 32 + (lane >> 4) * 16));
        }
        #pragma unroll
        for (int i = 0; i < 2; i++) {
            MMA16816(acc1[i][0], a[i][0], a[i][1], a[i][2], a[i][3], bb[0], bb[2]);
            MMA16816(acc1[i][1], a[i][0], a[i][1], a[i][2], a[i][3], bb[1], bb[3]);
        }
    }

    // mask: P[t,j] = (t>=j) ? G * exp(S_t - S_j) * dt_j : 0  -> Ps (bf16)
    int gid = lane >> 2, t4 = lane & 3;
    #pragma unroll
    for (int i = 0; i < 2; i++) {
        #pragma unroll
        for (int jd = 0; jd < 2; jd++) {
            int j0 = wn * 16 + jd * 8 + t4 * 2;
            #pragma unroll
            for (int hf = 0; hf < 2; hf++) {
                int t = wm * 32 + i * 16 + gid + hf * 8;
                float v0 = acc1[i][jd][hf * 2 + 0];
                float v1 = acc1[i][jd][hf * 2 + 1];
                float p0 = (t >= j0)     ? v0 * __expf(S[t] - S[j0])     * DT[j0]     : 0.f;
                float p1 = (t >= j0 + 1) ? v1 * __expf(S[t] - S[j0 + 1]) * DT[j0 + 1] : 0.f;
                __nv_bfloat162 pr;
                pr.x = __float2bfloat16(p0); pr.y = __float2bfloat16(p1);
                *(__nv_bfloat162*)(sm + AO_P + t * 144 + j0 * 2) = pr;
            }
        }
    }
    if (tid < 64) g_S[(size_t)bh * TT + chunk * CHK + tid] = S[tid];
    __syncthreads();

    // Wt[n][j] = B[j][n] * w_j  (bf16, transposed layout)
    for (int idx = tid; idx < 4096; idx += 256) {
        int j = idx >> 6, n = idx & 63;
        float bv = __bfloat162float(*(const __nv_bfloat16*)(sm + AO_B + j * 144 + n * 2));
        *(__nv_bfloat16*)(sm + AO_W + n * 144 + j * 2) = __float2bfloat16(bv * WJ[j]);
    }
    __syncthreads();

    // GEMM2: Y_intra = P @ X  (64x256, K=64 over j)  -> g_yi fp32
    {
        float acc[2][8][4];
        #pragma unroll
        for (int i = 0; i < 2; i++)
            #pragma unroll
            for (int j = 0; j < 8; j++)
                #pragma unroll
                for (int f = 0; f < 4; f++) acc[i][j][f] = 0.f;

        #pragma unroll
        for (int ks = 0; ks < 4; ks++) {
            uint32_t a[2][4];
            #pragma unroll
            for (int i = 0; i < 2; i++) {
                int row = wm * 32 + i * 16 + (lane & 15);
                LDM_X4(a[i][0], a[i][1], a[i][2], a[i][3],
                       base + AO_P + (uint32_t)(row * 144 + ks * 32 + (lane >> 4) * 16));
            }
            #pragma unroll
            for (int jj = 0; jj < 4; jj++) {
                int n0 = wn * 64 + jj * 16;
                int grp = lane >> 3, l8 = lane & 7;
                uint32_t addr = base + AO_X
                    + (uint32_t)(ks * 16 + (grp & 1) * 8 + l8) * 528
                    + (uint32_t)(n0 + (grp >> 1) * 8) * 2;
                uint32_t b0, b1, b2, b3;
                LDM_X4T(b0, b1, b2, b3, addr);
                #pragma unroll
                for (int i = 0; i < 2; i++) {
                    MMA16816(acc[i][jj * 2],     a[i][0], a[i][1], a[i][2], a[i][3], b0, b1);
                    MMA16816(acc[i][jj * 2 + 1], a[i][0], a[i][1], a[i][2], a[i][3], b2, b3);
                }
            }
        }
        #pragma unroll
        for (int i = 0; i < 2; i++)
            #pragma unroll
            for (int j8 = 0; j8 < 8; j8++)
                #pragma unroll
                for (int hf = 0; hf < 2; hf++) {
                    int t = wm * 32 + i * 16 + gid + hf * 8;
                    int d = wn * 64 + j8 * 8 + t4 * 2;
                    float2 v = make_float2(acc[i][j8][hf * 2], acc[i][j8][hf * 2 + 1]);
                    *(float2*)(g_yi + (rowbase + t) * DI + h * DH + d) = v;
                }
    }

    // GEMM3: H_c = Wt @ X  (64x256, K=64 over j)  -> g_hc fp32
    {
        float acc[2][8][4];
        #pragma unroll
        for (int i = 0; i < 2; i++)
            #pragma unroll
            for (int j = 0; j < 8; j++)
                #pragma unroll
                for (int f = 0; f < 4; f++) acc[i][j][f] = 0.f;

        #pragma unroll
        for (int ks = 0; ks < 4; ks++) {
            uint32_t a[2][4];
            #pragma unroll
            for (int i = 0; i < 2; i++) {
                int row = wm * 32 + i * 16 + (lane & 15);
                LDM_X4(a[i][0], a[i][1], a[i][2], a[i][3],
                       base + AO_W + (uint32_t)(row * 144 + ks * 32 + (lane >> 4) * 16));
            }
            #pragma unroll
            for (int jj = 0; jj < 4; jj++) {
                int n0 = wn * 64 + jj * 16;
                int grp = lane >> 3, l8 = lane & 7;
                uint32_t addr = base + AO_X
                    + (uint32_t)(ks * 16 + (grp & 1) * 8 + l8) * 528
                    + (uint32_t)(n0 + (grp >> 1) * 8) * 2;
                uint32_t b0, b1, b2, b3;
                LDM_X4T(b0, b1, b2, b3, addr);
                #pragma unroll
                for (int i = 0; i < 2; i++) {
                    MMA16816(acc[i][jj * 2],     a[i][0], a[i][1], a[i][2], a[i][3], b0, b1);
                    MMA16816(acc[i][jj * 2 + 1], a[i][0], a[i][1], a[i][2], a[i][3], b2, b3);
                }
            }
        }
        #pragma unroll
        for (int i = 0; i < 2; i++)
            #pragma unroll
            for (int j8 = 0; j8 < 8; j8++)
                #pragma unroll
                for (int hf = 0; hf < 2; hf++) {
                    int n = wm * 32 + i * 16 + gid + hf * 8;
                    int d = wn * 64 + j8 * 8 + t4 * 2;
                    float2 v = make_float2(acc[i][j8][hf * 2], acc[i][j8][hf * 2 + 1]);
                    *(float2*)(g_hc + (((size_t)bh * NCHKS + chunk) * DS + n) * DH + d) = v;
                }
    }
}

// ---------------- SSD phase B: cross-chunk state recurrence -----------------
// grid (4 d-slices, 8 h, 2 b), 256 threads; thread owns (n, 16 d) states.
__global__ void __launch_bounds__(256)
state_scan_k()
{
    int dsl = blockIdx.x, h = blockIdx.y, b = blockIdx.z;
    int bh = b * NH + h;
    int tid = threadIdx.x;
    int n = tid >> 2;
    int dbase = dsl * 64 + (tid & 3) * 16;

    float hst[16];
    #pragma unroll
    for (int q = 0; q < 16; q++) hst[q] = 0.f;

    for (int c = 0; c < NCHKS; c++) {
        float decay = __expf(g_S[(size_t)bh * TT + c * CHK + CHK - 1]);
        size_t hb = (((size_t)bh * NCHKS + c) * DS + n) * DH + dbase;
        #pragma unroll
        for (int q = 0; q < 8; q++) {
            __nv_bfloat162 pr;
            pr.x = __float2bfloat16(hst[q * 2]);
            pr.y = __float2bfloat16(hst[q * 2 + 1]);
            *(__nv_bfloat162*)(g_hin + hb + q * 2) = pr;
        }
        const float4* hc = (const float4*)(g_hc + hb);
        #pragma unroll
        for (int q = 0; q < 4; q++) {
            float4 v = hc[q];
            hst[q * 4 + 0] = decay * hst[q * 4 + 0] + v.x;
            hst[q * 4 + 1] = decay * hst[q * 4 + 1] + v.y;
            hst[q * 4 + 2] = decay * hst[q * 4 + 2] + v.z;
            hst[q * 4 + 3] = decay * hst[q * 4 + 3] + v.w;
        }
    }
}

// ---------------- SSD phase C: inter-chunk Y + combine + gate ---------------
#define CO_C 0
#define CO_H 9216
#define CO_S 43008
#define C_SMEM 43264

__global__ void __launch_bounds__(256)
chunk_inter_k(const float* __restrict__ Dp)
{
    extern __shared__ char sm[];
    uint32_t base = smem_u32(sm);
    float* S = (float*)(sm + CO_S);

    int tid = threadIdx.x;
    int wid = tid >> 5, lane = tid & 31;
    int wm = wid >> 2, wn = wid & 3;
    int chunk = blockIdx.x, h = blockIdx.y, b = blockIdx.z;
    int bh = b * NH + h;
    size_t rowbase = (size_t)b * TT + (size_t)chunk * CHK;

    const __nv_bfloat16* csrc = g_bcdt + rowbase * NCATP + 512 + h * 64;
    for (int i = tid; i < 512; i += 256) {
        int r = i >> 3, c = i & 7;
        CP_ASYNC16(base + CO_C + r * 144 + c * 16, csrc + (size_t)r * NCATP + c * 8);
    }
    const __nv_bfloat16* hsrc = g_hin + ((size_t)bh * NCHKS + chunk) * DS * DH;
    for (int i = tid; i < 2048; i += 256) {
        int r = i >> 5, c = i & 31;
        CP_ASYNC16(base + CO_H + r * 528 + c * 16, hsrc + (size_t)r * DH + c * 8);
    }
    if (tid < 64)
        CP_ASYNC4(base + CO_S + tid * 4, g_S + (size_t)bh * TT + chunk * CHK + tid);
    CP_COMMIT();
    CP_WAIT0();
    __syncthreads();

    float acc[2][8][4];
    #pragma unroll
    for (int i = 0; i < 2; i++)
        #pragma unroll
        for (int j = 0; j < 8; j++)
            #pragma unroll
            for (int f = 0; f < 4; f++) acc[i][j][f] = 0.f;

    #pragma unroll
    for (int ks = 0; ks < 4; ks++) {
        uint32_t a[2][4];
        #pragma unroll
        for (int i = 0; i < 2; i++) {
            int row = wm * 32 + i * 16 + (lane & 15);
            LDM_X4(a[i][0], a[i][1], a[i][2], a[i][3],
                   base + CO_C + (uint32_t)(row * 144 + ks * 32 + (lane >> 4) * 16));
        }
        #pragma unroll
        for (int jj = 0; jj < 4; jj++) {
            int n0 = wn * 64 + jj * 16;
            int grp = lane >> 3, l8 = lane & 7;
            uint32_t addr = base + CO_H
                + (uint32_t)(ks * 16 + (grp & 1) * 8 + l8) * 528
                + (uint32_t)(n0 + (grp >> 1) * 8) * 2;
            uint32_t b0, b1, b2, b3;
            LDM_X4T(b0, b1, b2, b3, addr);
            #pragma unroll
            for (int i = 0; i < 2; i++) {
                MMA16816(acc[i][jj * 2],     a[i][0], a[i][1], a[i][2], a[i][3], b0, b1);
                MMA16816(acc[i][jj * 2 + 1], a[i][0], a[i][1], a[i][2], a[i][3], b2, b3);
            }
        }
    }

    float Dh = Dp[h];
    int gid = lane >> 2, t4 = lane & 3;
    #pragma unroll
    for (int i = 0; i < 2; i++)
        #pragma unroll
        for (int j8 = 0; j8 < 8; j8++)
            #pragma unroll
            for (int hf = 0; hf < 2; hf++) {
                int t = wm * 32 + i * 16 + gid + hf * 8;
                int d = wn * 64 + j8 * 8 + t4 * 2;
                float et = __expf(S[t]);
                size_t gi = (rowbase + t) * DI + h * DH + d;
                float2 yi = *(const float2*)(g_yi + gi);
                __nv_bfloat162 xv = *(const __nv_bfloat162*)(g_xs + gi);
                float2 z2 = *(const float2*)(g_xz + (rowbase + t) * (2 * DI) + DI + h * DH + d);
                float y0 = acc[i][j8][hf * 2 + 0] * et + yi.x + Dh * __bfloat162float(xv.x);
                float y1 = acc[i][j8][hf * 2 + 1] * et + yi.y + Dh * __bfloat162float(xv.y);
                float s0 = z2.x / (1.f + __expf(-z2.x));
                float s1 = z2.y / (1.f + __expf(-z2.y));
                __nv_bfloat162 o;
                o.x = __float2bfloat16(y0 * s0);
                o.y = __float2bfloat16(y1 * s1);
                *(__nv_bfloat162*)(g_y + gi) = o;
            }
}

// ---------------- launch ----------------------------------------------------
extern "C" void kernel_launch(void* const* d_in, const int* in_sizes, int n_in,
                              void* d_out, int out_size)
{
    const float* x      = (const float*)d_in[0];
    const float* norm_w = (const float*)d_in[1];
    const float* in_w   = (const float*)d_in[2];
    const float* conv_w = (const float*)d_in[3];
    const float* conv_b = (const float*)d_in[4];
    const float* A_log  = (const float*)d_in[5];
    const float* B_w    = (const float*)d_in[6];
    const float* C_w    = (const float*)d_in[7];
    const float* dt_w   = (const float*)d_in[8];
    const float* dt_b   = (const float*)d_in[9];
    const float* Dp     = (const float*)d_in[10];
    const float* out_w  = (const float*)d_in[11];
    float* out = (float*)d_out;

    __nv_bfloat16 *p_xn, *p_xs, *p_y, *p_inw, *p_wcat, *p_outw, *p_bcdt;
    float *p_xz;
    cudaGetSymbolAddress((void**)&p_xn, g_xn);
    cudaGetSymbolAddress((void**)&p_xz, g_xz);
    cudaGetSymbolAddress((void**)&p_xs, g_xs);
    cudaGetSymbolAddress((void**)&p_bcdt, g_bcdt);
    cudaGetSymbolAddress((void**)&p_y, g_y);
    cudaGetSymbolAddress((void**)&p_inw, g_inw);
    cudaGetSymbolAddress((void**)&p_wcat, g_wcat);
    cudaGetSymbolAddress((void**)&p_outw, g_outw);

    cudaFuncSetAttribute(gemm_mma<false, false>, cudaFuncAttributeMaxDynamicSharedMemorySize, GEMM_SMEM);
    cudaFuncSetAttribute(gemm_mma<false, true>,  cudaFuncAttributeMaxDynamicSharedMemorySize, GEMM_SMEM);
    cudaFuncSetAttribute(gemm_mma<true, false>,  cudaFuncAttributeMaxDynamicSharedMemorySize, GEMM_SMEM);
    cudaFuncSetAttribute(chunk_intra_k, cudaFuncAttributeMaxDynamicSharedMemorySize, A_SMEM);
    cudaFuncSetAttribute(chunk_inter_k, cudaFuncAttributeMaxDynamicSharedMemorySize, C_SMEM);

    // [0] in_w -> bf16
    cvt_bf16_k<<<256, 256>>>(in_w, p_inw, 2 * DI * DM);
    // [1] RMSNorm -> bf16
    rmsnorm_k<<<NROWS, 256>>>(x, norm_w);
    // [2] out_w -> bf16
    cvt_bf16_k<<<256, 256>>>(out_w, p_outw, DM * DI);
    // [3] xz = xn @ in_w^T  (ncu capture slot)
    gemm_mma<false, false><<<dim3(4096 / BN, NROWS / BM), 256, GEMM_SMEM>>>(
        p_xn, p_inw, (void*)p_xz, nullptr, NROWS, 2 * DI, DM);
    // [4] fused [B|C|dt] weight
    build_wcat_k<<<256, 256>>>(B_w, C_w, dt_w);
    // [5] causal conv + SiLU -> bf16
    conv_silu_k<<<dim3(DI / 256, TT / 4, BSZ), 256>>>(conv_w, conv_b);
    // [6] [B | C | dt] = xs @ wcat^T  -> bf16
    gemm_mma<false, true><<<dim3(NCATP / BN, NROWS / BM), 256, GEMM_SMEM>>>(
        p_xs, p_wcat, (void*)p_bcdt, nullptr, NROWS, NCATP, DI);
    // [7] dt softplus
    dt_fin_k<<<(NROWS * NH + 255) / 256, 256>>>(dt_b);
    // [8] SSD phase A: intra-chunk + chunk state contributions
    chunk_intra_k<<<dim3(NCHKS, NH, BSZ), 256, A_SMEM>>>(A_log);
    // [9] SSD phase B: cross-chunk state recurrence
    state_scan_k<<<dim3(4, NH, BSZ), 256>>>();
    // [10] SSD phase C: inter-chunk Y + combine + gate -> g_y bf16
    chunk_inter_k<<<dim3(NCHKS, NH, BSZ), 256, C_SMEM>>>(Dp);
    // [11] out = y @ out_w^T + residual
    gemm_mma<true, false><<<dim3(1024 / BN, NROWS / BM), 256, GEMM_SMEM>>>(
        p_y, p_outw, (void*)out, x, NROWS, DM, DI);
}

// round 11
// speedup vs baseline: 2.4518x; 1.1416x over previous
#include <cuda_runtime.h>
#include <cuda_bf16.h>
#include <math.h>
#include <stdint.h>

// ---------------- problem constants ----------------------------------------
#define BSZ 2
#define TT 2048
#define DM 1024
#define DI 2048
#define NH 8
#define DS 64
#define DH 256
#define NROWS (BSZ*TT)          // 4096
#define EPSV 1e-6f
#define NCATP 1152              // B(512) | C(512) | dt(8) | pad -> 9*128
#define CHK 64
#define NCHKS (TT/CHK)          // 32

// ---------------- scratch (device globals) ---------------------------------
__device__ __nv_bfloat16 g_xn[(size_t)NROWS * DM];
__device__ __nv_bfloat16 g_xz[(size_t)NROWS * 2 * DI];             // bf16 now
__device__ __nv_bfloat16 g_xs[(size_t)NROWS * DI];
__device__ __nv_bfloat16 g_bcdt[(size_t)NROWS * NCATP];
__device__ __nv_bfloat16 g_y [(size_t)NROWS * DI];
__device__ __nv_bfloat16 g_yi[(size_t)NROWS * DI];                 // Y_intra bf16
__device__ float         g_hc [(size_t)16 * NCHKS * DS * DH];      // chunk state contribs
__device__ __nv_bfloat16 g_hin[(size_t)16 * NCHKS * DS * DH];      // per-chunk incoming state
__device__ float         g_S  [(size_t)16 * TT];                   // in-chunk cumsum of dt*A
__device__ __nv_bfloat16 g_inw [(size_t)(2*DI) * DM];
__device__ __nv_bfloat16 g_wcat[(size_t)NCATP * DI];
__device__ __nv_bfloat16 g_outw[(size_t)DM * DI];

// ---------------- PTX helpers ----------------------------------------------
__device__ __forceinline__ uint32_t smem_u32(const void* p) {
    uint32_t a;
    asm("{ .reg .u64 t; cvta.to.shared.u64 t, %1; cvt.u32.u64 %0, t; }" : "=r"(a) : "l"(p));
    return a;
}

#define CP_ASYNC16(dst, src) \
    asm volatile("cp.async.cg.shared.global [%0], [%1], 16;" :: "r"(dst), "l"(src) : "memory")
#define CP_ASYNC4(dst, src) \
    asm volatile("cp.async.ca.shared.global [%0], [%1], 4;" :: "r"(dst), "l"(src) : "memory")
#define CP_COMMIT() asm volatile("cp.async.commit_group;" ::: "memory")
#define CP_WAIT1()  asm volatile("cp.async.wait_group 1;" ::: "memory")
#define CP_WAIT0()  asm volatile("cp.async.wait_group 0;" ::: "memory")

#define LDM_X4(r0, r1, r2, r3, addr) \
    asm volatile("ldmatrix.sync.aligned.m8n8.x4.shared.b16 {%0,%1,%2,%3}, [%4];" \
                 : "=r"(r0), "=r"(r1), "=r"(r2), "=r"(r3) : "r"(addr))
#define LDM_X4T(r0, r1, r2, r3, addr) \
    asm volatile("ldmatrix.sync.aligned.m8n8.x4.trans.shared.b16 {%0,%1,%2,%3}, [%4];" \
                 : "=r"(r0), "=r"(r1), "=r"(r2), "=r"(r3) : "r"(addr))
#define LDM_X2(r0, r1, addr) \
    asm volatile("ldmatrix.sync.aligned.m8n8.x2.shared.b16 {%0,%1}, [%2];" \
                 : "=r"(r0), "=r"(r1) : "r"(addr))

#define MMA16816(d, a0, a1, a2, a3, b0, b1) \
    asm volatile("mma.sync.aligned.m16n8k16.row.col.f32.bf16.bf16.f32 " \
                 "{%0,%1,%2,%3}, {%4,%5,%6,%7}, {%8,%9}, {%0,%1,%2,%3};" \
                 : "+f"((d)[0]), "+f"((d)[1]), "+f"((d)[2]), "+f"((d)[3]) \
                 : "r"(a0), "r"(a1), "r"(a2), "r"(a3), "r"(b0), "r"(b1))

// ---------------- bf16 mma.sync GEMM: C[M,N] = A[M,K] @ W[N,K]^T (+Res) ----
#define BM 128
#define BN 128
#define BK64 64
#define ROWB 144
#define SA_BYTES (BM * ROWB)
#define STG_BYTES (2 * SA_BYTES)
#define NST 3
#define GEMM_SMEM (NST * STG_BYTES)      // 110592

template <bool ADD_RES, bool OUT_BF16>
__global__ void __launch_bounds__(256)
gemm_mma(const __nv_bfloat16* __restrict__ A, const __nv_bfloat16* __restrict__ W,
         void* __restrict__ Cout, const float* __restrict__ Res,
         int M, int N, int K)
{
    extern __shared__ char sm[];
    uint32_t base = smem_u32(sm);

    int tid = threadIdx.x;
    int wid = tid >> 5, lane = tid & 31;
    int wm = wid >> 2, wn = wid & 3;
    int m0 = blockIdx.y * BM;
    int n0 = blockIdx.x * BN;

    const __nv_bfloat16* Ag = A + (size_t)m0 * K;
    const __nv_bfloat16* Wg = W + (size_t)n0 * K;

    float acc[4][4][4];
    #pragma unroll
    for (int i = 0; i < 4; i++)
        #pragma unroll
        for (int j = 0; j < 4; j++)
            #pragma unroll
            for (int f = 0; f < 4; f++) acc[i][j][f] = 0.f;

    int nk = K / BK64;

    auto load_stage = [&](int s, int k0) {
        uint32_t sA = base + s * STG_BYTES;
        uint32_t sB = sA + SA_BYTES;
        #pragma unroll
        for (int it = 0; it < 4; it++) {
            int i = tid + it * 256;
            int r = i >> 3, c = i & 7;
            CP_ASYNC16(sA + r * ROWB + c * 16, Ag + (size_t)r * K + k0 + c * 8);
        }
        #pragma unroll
        for (int it = 0; it < 4; it++) {
            int i = tid + it * 256;
            int r = i >> 3, c = i & 7;
            CP_ASYNC16(sB + r * ROWB + c * 16, Wg + (size_t)r * K + k0 + c * 8);
        }
    };

    load_stage(0, 0);      CP_COMMIT();
    load_stage(1, BK64);   CP_COMMIT();

    int stg = 0;
    for (int kt = 0; kt < nk; kt++) {
        CP_WAIT1();
        __syncthreads();

        int s2 = stg + 2; if (s2 >= NST) s2 -= NST;
        if (kt + 2 < nk) load_stage(s2, (kt + 2) * BK64);
        CP_COMMIT();

        uint32_t sA = base + stg * STG_BYTES;
        uint32_t sB = sA + SA_BYTES;

        #pragma unroll
        for (int ks = 0; ks < 4; ks++) {
            int colA = ks * 32 + (lane >> 4) * 16;
            int colB = ks * 32 + ((lane >> 3) & 1) * 16;
            uint32_t a[4][4], b[4][2];
            #pragma unroll
            for (int i = 0; i < 4; i++) {
                int row = wm * 64 + i * 16 + (lane & 15);
                LDM_X4(a[i][0], a[i][1], a[i][2], a[i][3],
                       sA + (uint32_t)(row * ROWB + colA));
            }
            #pragma unroll
            for (int j = 0; j < 4; j++) {
                int row = wn * 32 + j * 8 + (lane & 7);
                LDM_X2(b[j][0], b[j][1],
                       sB + (uint32_t)(row * ROWB + colB));
            }
            #pragma unroll
            for (int i = 0; i < 4; i++)
                #pragma unroll
                for (int j = 0; j < 4; j++)
                    MMA16816(acc[i][j], a[i][0], a[i][1], a[i][2], a[i][3],
                             b[j][0], b[j][1]);
        }
        stg++; if (stg >= NST) stg -= NST;
    }

    int gid = lane >> 2, t4 = lane & 3;
    #pragma unroll
    for (int i = 0; i < 4; i++) {
        int row0 = m0 + wm * 64 + i * 16 + gid;
        #pragma unroll
        for (int j = 0; j < 4; j++) {
            int col = n0 + wn * 32 + j * 8 + t4 * 2;
            size_t i0 = (size_t)row0 * N + col;
            size_t i1 = (size_t)(row0 + 8) * N + col;
            float2 v0 = make_float2(acc[i][j][0], acc[i][j][1]);
            float2 v1 = make_float2(acc[i][j][2], acc[i][j][3]);
            if (ADD_RES) {
                float2 r0 = *(const float2*)(Res + i0);
                float2 r1 = *(const float2*)(Res + i1);
                v0.x += r0.x; v0.y += r0.y;
                v1.x += r1.x; v1.y += r1.y;
            }
            if (OUT_BF16) {
                __nv_bfloat16* Cb = (__nv_bfloat16*)Cout;
                __nv_bfloat162 o0, o1;
                o0.x = __float2bfloat16(v0.x); o0.y = __float2bfloat16(v0.y);
                o1.x = __float2bfloat16(v1.x); o1.y = __float2bfloat16(v1.y);
                *(__nv_bfloat162*)(Cb + i0) = o0;
                *(__nv_bfloat162*)(Cb + i1) = o1;
            } else {
                float* Cf = (float*)Cout;
                *(float2*)(Cf + i0) = v0;
                *(float2*)(Cf + i1) = v1;
            }
        }
    }
}

// ---------------- weight conversion (vectorized) ----------------------------
__global__ void cvt_bf16_k(const float4* __restrict__ in, __nv_bfloat162* __restrict__ out, int n4)
{
    for (int i = blockIdx.x * 256 + threadIdx.x; i < n4; i += gridDim.x * 256) {
        float4 v = in[i];
        __nv_bfloat162 o0, o1;
        o0.x = __float2bfloat16(v.x); o0.y = __float2bfloat16(v.y);
        o1.x = __float2bfloat16(v.z); o1.y = __float2bfloat16(v.w);
        out[2 * i] = o0; out[2 * i + 1] = o1;
    }
}

__global__ void build_wcat_k(const float* __restrict__ Bw, const float* __restrict__ Cw,
                             const float* __restrict__ dtw)
{
    int n4 = NCATP * DI / 4;
    for (int i = blockIdx.x * 256 + threadIdx.x; i < n4; i += gridDim.x * 256) {
        int r = i >> 9;                 // DI/4 = 512 groups per row
        int kk = (i & 511) * 4;
        float4 v;
        if (r < 512)       v = *(const float4*)(Bw + (size_t)r * DI + kk);
        else if (r < 1024) v = *(const float4*)(Cw + (size_t)(r - 512) * DI + kk);
        else if (r < 1032) v = *(const float4*)(dtw + (size_t)(r - 1024) * DI + kk);
        else               v = make_float4(0.f, 0.f, 0.f, 0.f);
        __nv_bfloat162 o0, o1;
        o0.x = __float2bfloat16(v.x); o0.y = __float2bfloat16(v.y);
        o1.x = __float2bfloat16(v.z); o1.y = __float2bfloat16(v.w);
        ((__nv_bfloat162*)g_wcat)[2 * i] = o0;
        ((__nv_bfloat162*)g_wcat)[2 * i + 1] = o1;
    }
}

// ---------------- RMSNorm (float4, writes bf16) -----------------------------
__global__ void rmsnorm_k(const float* __restrict__ x, const float* __restrict__ w)
{
    int row = blockIdx.x;
    int tid = threadIdx.x;
    const float4* xr = (const float4*)(x + (size_t)row * DM);
    float4 v = xr[tid];
    float s = v.x * v.x + v.y * v.y + v.z * v.z + v.w * v.w;
    __shared__ float red[8];
    #pragma unroll
    for (int o = 16; o; o >>= 1) s += __shfl_xor_sync(0xffffffffu, s, o);
    if ((tid & 31) == 0) red[tid >> 5] = s;
    __syncthreads();
    if (tid < 8) {
        float t = red[tid];
        #pragma unroll
        for (int o = 4; o; o >>= 1) t += __shfl_xor_sync(0xffu, t, o);
        if (tid == 0) red[0] = rsqrtf(t / (float)DM + EPSV);
    }
    __syncthreads();
    float sc = red[0];
    float4 wv = ((const float4*)w)[tid];
    __nv_bfloat162 o0, o1;
    o0.x = __float2bfloat16(v.x * sc * wv.x);
    o0.y = __float2bfloat16(v.y * sc * wv.y);
    o1.x = __float2bfloat16(v.z * sc * wv.z);
    o1.y = __float2bfloat16(v.w * sc * wv.w);
    __nv_bfloat162* orow = (__nv_bfloat162*)(g_xn + (size_t)row * DM);
    orow[tid * 2] = o0;
    orow[tid * 2 + 1] = o1;
}

// ---------------- causal depthwise conv (K=4) + bias + SiLU -> bf16 ---------
__global__ void conv_silu_k(const float* __restrict__ cw, const float* __restrict__ cb)
{
    int c = blockIdx.x * 256 + threadIdx.x;
    int t0 = blockIdx.y * 4;
    int b = blockIdx.z;
    float4 w = ((const float4*)cw)[c];
    float bias = cb[c];
    size_t colbase = (size_t)b * TT * (2 * DI) + c;
    const size_t stride = 2 * DI;

    float xv[7];
    #pragma unroll
    for (int k = 0; k < 7; k++) {
        int t = t0 - 3 + k;
        xv[k] = (t >= 0) ? __bfloat162float(g_xz[colbase + (size_t)t * stride]) : 0.f;
    }
    size_t obase = ((size_t)b * TT + t0) * DI + c;
    #pragma unroll
    for (int i = 0; i < 4; i++) {
        float acc = bias + w.x * xv[i] + w.y * xv[i + 1] + w.z * xv[i + 2] + w.w * xv[i + 3];
        float sig = 1.f / (1.f + __expf(-acc));
        g_xs[obase + (size_t)i * DI] = __float2bfloat16(acc * sig);
    }
}

// ---------------- SSD phase A: intra-chunk + state contributions ------------
#define AO_C 0
#define AO_B 9216
#define AO_P 18432
#define AO_W 27648
#define AO_X 36864
#define AO_S 70656
#define AO_DT 70912
#define AO_WJ 71168
#define A_SMEM 71424

__global__ void __launch_bounds__(256)
chunk_intra_k(const float* __restrict__ A_log, const float* __restrict__ dtb)
{
    extern __shared__ char sm[];
    uint32_t base = smem_u32(sm);
    float* S  = (float*)(sm + AO_S);
    float* DT = (float*)(sm + AO_DT);
    float* WJ = (float*)(sm + AO_WJ);

    int tid = threadIdx.x;
    int wid = tid >> 5, lane = tid & 31;
    int wm = wid >> 2, wn = wid & 3;
    int chunk = blockIdx.x, h = blockIdx.y, b = blockIdx.z;
    int bh = b * NH + h;
    size_t rowbase = (size_t)b * TT + (size_t)chunk * CHK;

    const __nv_bfloat16* bsrc = g_bcdt + rowbase * NCATP + h * 64;
    for (int i = tid; i < 512; i += 256) {
        int r = i >> 3, c = i & 7;
        CP_ASYNC16(base + AO_B + r * 144 + c * 16, bsrc + (size_t)r * NCATP + c * 8);
        CP_ASYNC16(base + AO_C + r * 144 + c * 16, bsrc + (size_t)r * NCATP + 512 + c * 8);
    }
    for (int i = tid; i < 2048; i += 256) {
        int r = i >> 5, c = i & 31;
        CP_ASYNC16(base + AO_X + r * 528 + c * 16, g_xs + (rowbase + r) * DI + h * DH + c * 8);
    }
    CP_COMMIT();

    // dt = softplus(raw + bias), computed inline (dt_fin fused away)
    if (tid < 64) {
        float v = __bfloat162float(g_bcdt[(rowbase + tid) * NCATP + 1024 + h]) + dtb[h];
        DT[tid] = (v > 20.f) ? v : log1pf(expf(v));
    }
    CP_WAIT0();
    __syncthreads();

    float Ah = -__expf(A_log[h]);
    if (wid == 0) {
        float a0 = DT[lane] * Ah, a1 = DT[lane + 32] * Ah;
        #pragma unroll
        for (int off = 1; off < 32; off <<= 1) {
            float u0 = __shfl_up_sync(0xffffffffu, a0, off);
            float u1 = __shfl_up_sync(0xffffffffu, a1, off);
            if (lane >= off) { a0 += u0; a1 += u1; }
        }
        float tot = __shfl_sync(0xffffffffu, a0, 31);
        a1 += tot;
        S[lane] = a0; S[lane + 32] = a1;
    }
    __syncthreads();
    if (tid < 64) WJ[tid] = __expf(S[63] - S[tid]) * DT[tid];

    // GEMM1: G = C @ B^T
    float acc1[2][2][4];
    #pragma unroll
    for (int i = 0; i < 2; i++)
        #pragma unroll
        for (int j = 0; j < 2; j++)
            #pragma unroll
            for (int f = 0; f < 4; f++) acc1[i][j][f] = 0.f;

    #pragma unroll
    for (int ks = 0; ks < 4; ks++) {
        uint32_t a[2][4], bb[4];
        #pragma unroll
        for (int i = 0; i < 2; i++) {
            int row = wm * 32 + i * 16 + (lane & 15);
            LDM_X4(a[i][0], a[i][1], a[i][2], a[i][3],
                   base + AO_C + (uint32_t)(row * 144 + ks * 32 + (lane >> 4) * 16));
        }
        {
            int row = wn * 16 + (lane & 15);
            LDM_X4(bb[0], bb[1], bb[2], bb[3],
                   base + AO_B + (uint32_t)(row * 144 + ks * 32 + (lane >> 4) * 16));
        }
        #pragma unroll
        for (int i = 0; i < 2; i++) {
            MMA16816(acc1[i][0], a[i][0], a[i][1], a[i][2], a[i][3], bb[0], bb[2]);
            MMA16816(acc1[i][1], a[i][0], a[i][1], a[i][2], a[i][3], bb[1], bb[3]);
        }
    }

    int gid = lane >> 2, t4 = lane & 3;
    #pragma unroll
    for (int i = 0; i < 2; i++) {
        #pragma unroll
        for (int jd = 0; jd < 2; jd++) {
            int j0 = wn * 16 + jd * 8 + t4 * 2;
            #pragma unroll
            for (int hf = 0; hf < 2; hf++) {
                int t = wm * 32 + i * 16 + gid + hf * 8;
                float v0 = acc1[i][jd][hf * 2 + 0];
                float v1 = acc1[i][jd][hf * 2 + 1];
                float p0 = (t >= j0)     ? v0 * __expf(S[t] - S[j0])     * DT[j0]     : 0.f;
                float p1 = (t >= j0 + 1) ? v1 * __expf(S[t] - S[j0 + 1]) * DT[j0 + 1] : 0.f;
                __nv_bfloat162 pr;
                pr.x = __float2bfloat16(p0); pr.y = __float2bfloat16(p1);
                *(__nv_bfloat162*)(sm + AO_P + t * 144 + j0 * 2) = pr;
            }
        }
    }
    if (tid < 64) g_S[(size_t)bh * TT + chunk * CHK + tid] = S[tid];
    __syncthreads();

    for (int idx = tid; idx < 4096; idx += 256) {
        int j = idx >> 6, n = idx & 63;
        float bv = __bfloat162float(*(const __nv_bfloat16*)(sm + AO_B + j * 144 + n * 2));
        *(__nv_bfloat16*)(sm + AO_W + n * 144 + j * 2) = __float2bfloat16(bv * WJ[j]);
    }
    __syncthreads();

    // GEMM2: Y_intra = P @ X -> g_yi (bf16)
    {
        float acc[2][8][4];
        #pragma unroll
        for (int i = 0; i < 2; i++)
            #pragma unroll
            for (int j = 0; j < 8; j++)
                #pragma unroll
                for (int f = 0; f < 4; f++) acc[i][j][f] = 0.f;

        #pragma unroll
        for (int ks = 0; ks < 4; ks++) {
            uint32_t a[2][4];
            #pragma unroll
            for (int i = 0; i < 2; i++) {
                int row = wm * 32 + i * 16 + (lane & 15);
                LDM_X4(a[i][0], a[i][1], a[i][2], a[i][3],
                       base + AO_P + (uint32_t)(row * 144 + ks * 32 + (lane >> 4) * 16));
            }
            #pragma unroll
            for (int jj = 0; jj < 4; jj++) {
                int n0 = wn * 64 + jj * 16;
                int grp = lane >> 3, l8 = lane & 7;
                uint32_t addr = base + AO_X
                    + (uint32_t)(ks * 16 + (grp & 1) * 8 + l8) * 528
                    + (uint32_t)(n0 + (grp >> 1) * 8) * 2;
                uint32_t b0, b1, b2, b3;
                LDM_X4T(b0, b1, b2, b3, addr);
                #pragma unroll
                for (int i = 0; i < 2; i++) {
                    MMA16816(acc[i][jj * 2],     a[i][0], a[i][1], a[i][2], a[i][3], b0, b1);
                    MMA16816(acc[i][jj * 2 + 1], a[i][0], a[i][1], a[i][2], a[i][3], b2, b3);
                }
            }
        }
        #pragma unroll
        for (int i = 0; i < 2; i++)
            #pragma unroll
            for (int j8 = 0; j8 < 8; j8++)
                #pragma unroll
                for (int hf = 0; hf < 2; hf++) {
                    int t = wm * 32 + i * 16 + gid + hf * 8;
                    int d = wn * 64 + j8 * 8 + t4 * 2;
                    __nv_bfloat162 v;
                    v.x = __float2bfloat16(acc[i][j8][hf * 2]);
                    v.y = __float2bfloat16(acc[i][j8][hf * 2 + 1]);
                    *(__nv_bfloat162*)(g_yi + (rowbase + t) * DI + h * DH + d) = v;
                }
    }

    // GEMM3: H_c = Wt @ X -> g_hc fp32
    {
        float acc[2][8][4];
        #pragma unroll
        for (int i = 0; i < 2; i++)
            #pragma unroll
            for (int j = 0; j < 8; j++)
                #pragma unroll
                for (int f = 0; f < 4; f++) acc[i][j][f] = 0.f;

        #pragma unroll
        for (int ks = 0; ks < 4; ks++) {
            uint32_t a[2][4];
            #pragma unroll
            for (int i = 0; i < 2; i++) {
                int row = wm * 32 + i * 16 + (lane & 15);
                LDM_X4(a[i][0], a[i][1], a[i][2], a[i][3],
                       base + AO_W + (uint32_t)(row * 144 + ks * 32 + (lane >> 4) * 16));
            }
            #pragma unroll
            for (int jj = 0; jj < 4; jj++) {
                int n0 = wn * 64 + jj * 16;
                int grp = lane >> 3, l8 = lane & 7;
                uint32_t addr = base + AO_X
                    + (uint32_t)(ks * 16 + (grp & 1) * 8 + l8) * 528
                    + (uint32_t)(n0 + (grp >> 1) * 8) * 2;
                uint32_t b0, b1, b2, b3;
                LDM_X4T(b0, b1, b2, b3, addr);
                #pragma unroll
                for (int i = 0; i < 2; i++) {
                    MMA16816(acc[i][jj * 2],     a[i][0], a[i][1], a[i][2], a[i][3], b0, b1);
                    MMA16816(acc[i][jj * 2 + 1], a[i][0], a[i][1], a[i][2], a[i][3], b2, b3);
                }
            }
        }
        #pragma unroll
        for (int i = 0; i < 2; i++)
            #pragma unroll
            for (int j8 = 0; j8 < 8; j8++)
                #pragma unroll
                for (int hf = 0; hf < 2; hf++) {
                    int n = wm * 32 + i * 16 + gid + hf * 8;
                    int d = wn * 64 + j8 * 8 + t4 * 2;
                    float2 v = make_float2(acc[i][j8][hf * 2], acc[i][j8][hf * 2 + 1]);
                    *(float2*)(g_hc + (((size_t)bh * NCHKS + chunk) * DS + n) * DH + d) = v;
                }
    }
}

// ---------------- SSD phase B: cross-chunk state recurrence -----------------
__global__ void __launch_bounds__(256)
state_scan_k()
{
    int dsl = blockIdx.x, h = blockIdx.y, b = blockIdx.z;
    int bh = b * NH + h;
    int tid = threadIdx.x;
    int n = tid >> 2;
    int dbase = dsl * 64 + (tid & 3) * 16;

    float hst[16];
    #pragma unroll
    for (int q = 0; q < 16; q++) hst[q] = 0.f;

    for (int c = 0; c < NCHKS; c++) {
        float decay = __expf(g_S[(size_t)bh * TT + c * CHK + CHK - 1]);
        size_t hb = (((size_t)bh * NCHKS + c) * DS + n) * DH + dbase;
        #pragma unroll
        for (int q = 0; q < 8; q++) {
            __nv_bfloat162 pr;
            pr.x = __float2bfloat16(hst[q * 2]);
            pr.y = __float2bfloat16(hst[q * 2 + 1]);
            *(__nv_bfloat162*)(g_hin + hb + q * 2) = pr;
        }
        const float4* hc = (const float4*)(g_hc + hb);
        #pragma unroll
        for (int q = 0; q < 4; q++) {
            float4 v = hc[q];
            hst[q * 4 + 0] = decay * hst[q * 4 + 0] + v.x;
            hst[q * 4 + 1] = decay * hst[q * 4 + 1] + v.y;
            hst[q * 4 + 2] = decay * hst[q * 4 + 2] + v.z;
            hst[q * 4 + 3] = decay * hst[q * 4 + 3] + v.w;
        }
    }
}

// ---------------- SSD phase C: inter-chunk Y + combine + gate ---------------
#define CO_C 0
#define CO_H 9216
#define CO_S 43008
#define C_SMEM 43264

__global__ void __launch_bounds__(256)
chunk_inter_k(const float* __restrict__ Dp)
{
    extern __shared__ char sm[];
    uint32_t base = smem_u32(sm);
    float* S = (float*)(sm + CO_S);

    int tid = threadIdx.x;
    int wid = tid >> 5, lane = tid & 31;
    int wm = wid >> 2, wn = wid & 3;
    int chunk = blockIdx.x, h = blockIdx.y, b = blockIdx.z;
    int bh = b * NH + h;
    size_t rowbase = (size_t)b * TT + (size_t)chunk * CHK;

    const __nv_bfloat16* csrc = g_bcdt + rowbase * NCATP + 512 + h * 64;
    for (int i = tid; i < 512; i += 256) {
        int r = i >> 3, c = i & 7;
        CP_ASYNC16(base + CO_C + r * 144 + c * 16, csrc + (size_t)r * NCATP + c * 8);
    }
    const __nv_bfloat16* hsrc = g_hin + ((size_t)bh * NCHKS + chunk) * DS * DH;
    for (int i = tid; i < 2048; i += 256) {
        int r = i >> 5, c = i & 31;
        CP_ASYNC16(base + CO_H + r * 528 + c * 16, hsrc + (size_t)r * DH + c * 8);
    }
    if (tid < 64)
        CP_ASYNC4(base + CO_S + tid * 4, g_S + (size_t)bh * TT + chunk * CHK + tid);
    CP_COMMIT();
    CP_WAIT0();
    __syncthreads();

    float acc[2][8][4];
    #pragma unroll
    for (int i = 0; i < 2; i++)
        #pragma unroll
        for (int j = 0; j < 8; j++)
            #pragma unroll
            for (int f = 0; f < 4; f++) acc[i][j][f] = 0.f;

    #pragma unroll
    for (int ks = 0; ks < 4; ks++) {
        uint32_t a[2][4];
        #pragma unroll
        for (int i = 0; i < 2; i++) {
            int row = wm * 32 + i * 16 + (lane & 15);
            LDM_X4(a[i][0], a[i][1], a[i][2], a[i][3],
                   base + CO_C + (uint32_t)(row * 144 + ks * 32 + (lane >> 4) * 16));
        }
        #pragma unroll
        for (int jj = 0; jj < 4; jj++) {
            int n0 = wn * 64 + jj * 16;
            int grp = lane >> 3, l8 = lane & 7;
            uint32_t addr = base + CO_H
                + (uint32_t)(ks * 16 + (grp & 1) * 8 + l8) * 528
                + (uint32_t)(n0 + (grp >> 1) * 8) * 2;
            uint32_t b0, b1, b2, b3;
            LDM_X4T(b0, b1, b2, b3, addr);
            #pragma unroll
            for (int i = 0; i < 2; i++) {
                MMA16816(acc[i][jj * 2],     a[i][0], a[i][1], a[i][2], a[i][3], b0, b1);
                MMA16816(acc[i][jj * 2 + 1], a[i][0], a[i][1], a[i][2], a[i][3], b2, b3);
            }
        }
    }

    float Dh = Dp[h];
    int gid = lane >> 2, t4 = lane & 3;
    #pragma unroll
    for (int i = 0; i < 2; i++)
        #pragma unroll
        for (int j8 = 0; j8 < 8; j8++)
            #pragma unroll
            for (int hf = 0; hf < 2; hf++) {
                int t = wm * 32 + i * 16 + gid + hf * 8;
                int d = wn * 64 + j8 * 8 + t4 * 2;
                float et = __expf(S[t]);
                size_t gi = (rowbase + t) * DI + h * DH + d;
                __nv_bfloat162 yi = *(const __nv_bfloat162*)(g_yi + gi);
                __nv_bfloat162 xv = *(const __nv_bfloat162*)(g_xs + gi);
                __nv_bfloat162 z2 = *(const __nv_bfloat162*)(g_xz + (rowbase + t) * (2 * DI) + DI + h * DH + d);
                float z0 = __bfloat162float(z2.x), z1 = __bfloat162float(z2.y);
                float y0 = acc[i][j8][hf * 2 + 0] * et + __bfloat162float(yi.x) + Dh * __bfloat162float(xv.x);
                float y1 = acc[i][j8][hf * 2 + 1] * et + __bfloat162float(yi.y) + Dh * __bfloat162float(xv.y);
                float s0 = z0 / (1.f + __expf(-z0));
                float s1 = z1 / (1.f + __expf(-z1));
                __nv_bfloat162 o;
                o.x = __float2bfloat16(y0 * s0);
                o.y = __float2bfloat16(y1 * s1);
                *(__nv_bfloat162*)(g_y + gi) = o;
            }
}

// ---------------- launch ----------------------------------------------------
extern "C" void kernel_launch(void* const* d_in, const int* in_sizes, int n_in,
                              void* d_out, int out_size)
{
    const float* x      = (const float*)d_in[0];
    const float* norm_w = (const float*)d_in[1];
    const float* in_w   = (const float*)d_in[2];
    const float* conv_w = (const float*)d_in[3];
    const float* conv_b = (const float*)d_in[4];
    const float* A_log  = (const float*)d_in[5];
    const float* B_w    = (const float*)d_in[6];
    const float* C_w    = (const float*)d_in[7];
    const float* dt_w   = (const float*)d_in[8];
    const float* dt_b   = (const float*)d_in[9];
    const float* Dp     = (const float*)d_in[10];
    const float* out_w  = (const float*)d_in[11];
    float* out = (float*)d_out;

    __nv_bfloat16 *p_xn, *p_xs, *p_y, *p_inw, *p_wcat, *p_outw, *p_bcdt, *p_xz;
    cudaGetSymbolAddress((void**)&p_xn, g_xn);
    cudaGetSymbolAddress((void**)&p_xz, g_xz);
    cudaGetSymbolAddress((void**)&p_xs, g_xs);
    cudaGetSymbolAddress((void**)&p_bcdt, g_bcdt);
    cudaGetSymbolAddress((void**)&p_y, g_y);
    cudaGetSymbolAddress((void**)&p_inw, g_inw);
    cudaGetSymbolAddress((void**)&p_wcat, g_wcat);
    cudaGetSymbolAddress((void**)&p_outw, g_outw);

    cudaFuncSetAttribute(gemm_mma<false, true>,  cudaFuncAttributeMaxDynamicSharedMemorySize, GEMM_SMEM);
    cudaFuncSetAttribute(gemm_mma<true, false>,  cudaFuncAttributeMaxDynamicSharedMemorySize, GEMM_SMEM);
    cudaFuncSetAttribute(chunk_intra_k, cudaFuncAttributeMaxDynamicSharedMemorySize, A_SMEM);
    cudaFuncSetAttribute(chunk_inter_k, cudaFuncAttributeMaxDynamicSharedMemorySize, C_SMEM);

    // [0] in_w -> bf16
    cvt_bf16_k<<<256, 256>>>((const float4*)in_w, (__nv_bfloat162*)p_inw, 2 * DI * DM / 4);
    // [1] RMSNorm -> bf16
    rmsnorm_k<<<NROWS, 256>>>(x, norm_w);
    // [2] out_w -> bf16
    cvt_bf16_k<<<256, 256>>>((const float4*)out_w, (__nv_bfloat162*)p_outw, DM * DI / 4);
    // [3] xz = xn @ in_w^T -> bf16  (ncu capture slot)
    gemm_mma<false, true><<<dim3(4096 / BN, NROWS / BM), 256, GEMM_SMEM>>>(
        p_xn, p_inw, (void*)p_xz, nullptr, NROWS, 2 * DI, DM);
    // [4] fused [B|C|dt] weight
    build_wcat_k<<<256, 256>>>(B_w, C_w, dt_w);
    // [5] causal conv + SiLU -> bf16
    conv_silu_k<<<dim3(DI / 256, TT / 4, BSZ), 256>>>(conv_w, conv_b);
    // [6] [B | C | dt] = xs @ wcat^T -> bf16
    gemm_mma<false, true><<<dim3(NCATP / BN, NROWS / BM), 256, GEMM_SMEM>>>(
        p_xs, p_wcat, (void*)p_bcdt, nullptr, NROWS, NCATP, DI);
    // [7] SSD phase A: intra-chunk + chunk state contributions (dt softplus fused)
    chunk_intra_k<<<dim3(NCHKS, NH, BSZ), 256, A_SMEM>>>(A_log, dt_b);
    // [8] SSD phase B: cross-chunk state recurrence
    state_scan_k<<<dim3(4, NH, BSZ), 256>>>();
    // [9] SSD phase C: inter-chunk Y + combine + gate -> g_y bf16
    chunk_inter_k<<<dim3(NCHKS, NH, BSZ), 256, C_SMEM>>>(Dp);
    // [10] out = y @ out_w^T + residual
    gemm_mma<true, false><<<dim3(1024 / BN, NROWS / BM), 256, GEMM_SMEM>>>(
        p_y, p_outw, (void*)out, x, NROWS, DM, DI);
}